// round 6
// baseline (speedup 1.0000x reference)
#include <cuda_runtime.h>
#include <cstdint>

#define Bsz 4
#define Cin 64
#define OUTC 64
#define H 256
#define W 256
#define HW (H*W)

#define MTILE 128          // pixels per CTA (half row)
#define SSTRIDE 68         // ssm row stride in floats: [px][c], 64+4 pad
#define WSTRIDE 72         // wsm row stride: [c][o], 64+8 pad

#define OWS 40             // offsets-kernel weight smem stride (24 + 16 pad; 40%32==8 -> conflict-free)
#define NJ 24              // 18 offset channels padded to 24

// Scratch (device globals — no allocation allowed)
__device__ float g_offs[(size_t)Bsz * 18 * HW];        // offset conv output (fp32-accurate)
__device__ float g_wT[9 * Cin * OUTC];                 // w_def -> [k][c][o] (tf32 bits)
__device__ float g_xt[(size_t)Bsz * HW * Cin];         // x transposed to NHWC (64MB)
__device__ float g_woT[2 * 9 * Cin * NJ];              // w_off -> [hi/lo][k][c][j] (tf32 bits)

// ---------------------------------------------------------------------------
// tf32 helpers
// ---------------------------------------------------------------------------
__device__ __forceinline__ uint32_t f32_to_tf32(float v) {
    uint32_t t;
    asm("cvt.rna.tf32.f32 %0, %1;" : "=r"(t) : "f"(v));
    return t;
}

__device__ __forceinline__ void mma_tf32(float* d, const uint32_t* a, const uint32_t* b) {
    asm volatile(
        "mma.sync.aligned.m16n8k8.row.col.f32.tf32.tf32.f32 "
        "{%0,%1,%2,%3}, {%4,%5,%6,%7}, {%8,%9}, {%0,%1,%2,%3};"
        : "+f"(d[0]), "+f"(d[1]), "+f"(d[2]), "+f"(d[3])
        : "r"(a[0]), "r"(a[1]), "r"(a[2]), "r"(a[3]),
          "r"(b[0]), "r"(b[1]));
}

// ---------------------------------------------------------------------------
// Kernel 0a: transpose w_def [o][c][ki][kj] -> g_wT[k][c][o], tf32-rounded
// ---------------------------------------------------------------------------
__global__ void transpose_wdef_kernel(const float* __restrict__ w_def) {
    int idx = blockIdx.x * 256 + threadIdx.x;
    if (idx >= OUTC * Cin * 9) return;
    int o = idx / (Cin * 9);
    int rem = idx - o * (Cin * 9);
    int c = rem / 9;
    int k = rem - c * 9;
    g_wT[(k * Cin + c) * OUTC + o] = __uint_as_float(f32_to_tf32(w_def[idx]));
}

// ---------------------------------------------------------------------------
// Kernel 0b: split w_off [j][c][ki][kj] -> g_woT[{hi,lo}][k][c][j] (tf32 bits)
// ---------------------------------------------------------------------------
__global__ void prep_woff_kernel(const float* __restrict__ w_off) {
    int idx = blockIdx.x * 256 + threadIdx.x;       // 9*64*24 = 13824
    if (idx >= 9 * Cin * NJ) return;
    int k = idx / (Cin * NJ);
    int rem = idx - k * (Cin * NJ);
    int c = rem / NJ;
    int j = rem - c * NJ;
    float v = (j < 18) ? w_off[(size_t)j * Cin * 9 + c * 9 + k] : 0.f;
    uint32_t hib = f32_to_tf32(v);
    float lo = v - __uint_as_float(hib);
    g_woT[(k * Cin + c) * NJ + j] = __uint_as_float(hib);
    g_woT[9 * Cin * NJ + (k * Cin + c) * NJ + j] = __uint_as_float(f32_to_tf32(lo));
}

// ---------------------------------------------------------------------------
// Kernel 0c: transpose x NCHW -> NHWC (g_xt)
// ---------------------------------------------------------------------------
__global__ void __launch_bounds__(256) transpose_x_kernel(const float* __restrict__ x) {
    __shared__ float t[Cin][33];
    int tid = threadIdx.x;
    int bx = blockIdx.x;
    int wt = (bx & 7) << 5;
    int h = (bx >> 3) & (H - 1);
    int b = bx >> 11;

    const float* xb = x + (size_t)b * Cin * HW + h * W + wt;
#pragma unroll
    for (int it = 0; it < 8; it++) {
        int c = it * 8 + (tid >> 5);
        int w = tid & 31;
        t[c][w] = xb[(size_t)c * HW + w];
    }
    __syncthreads();
    float* xo = g_xt + ((size_t)(b * H + h) * W + wt) * Cin;
#pragma unroll
    for (int it = 0; it < 8; it++) {
        int w = it * 4 + (tid >> 6);
        int c = tid & 63;
        xo[(size_t)w * Cin + c] = t[c][w];
    }
}

// ---------------------------------------------------------------------------
// Kernel 1: offsets conv via tf32 split-precision MMA (fp32-accurate result).
// CTA: 128 px, 256 thr = 8 warps; warp = 16 px x 24 (18) outputs.
// Per tap: stage A_hi (shifted NHWC rows, coalesced), MMA vs B_hi and B_lo;
// restage A_lo, MMA vs B_hi.  D = Ah*Bh + Ah*Bl + Al*Bh  (error ~2^-22).
// ---------------------------------------------------------------------------
#define OFF_SSM_U32 (MTILE * SSTRIDE)
#define OFF_DSMEM ((OFF_SSM_U32 + 2 * Cin * OWS) * 4)   // 55296 B

__global__ void __launch_bounds__(256) offsets_kernel(
    const float* __restrict__ b_off)
{
    extern __shared__ uint32_t dsm[];
    uint32_t* ssm = dsm;                        // [px][c] stride 68 (A hi, then A lo)
    uint32_t* wsmh = dsm + OFF_SSM_U32;         // [c][j] stride 40, hi
    uint32_t* wsml = wsmh + Cin * OWS;          // lo

    int tid = threadIdx.x;
    int bx = blockIdx.x;
    int wt = (bx & 1) << 7;
    int h = (bx >> 1) & (H - 1);
    int b = bx >> 9;

    int lane = tid & 31;
    int wid = tid >> 5;
    int r = lane & 3;
    int g = lane >> 2;
    int px0 = wid << 4;                 // warp's 16-px tile (sampling AND mma)

    float acc[3][4];
#pragma unroll
    for (int ni = 0; ni < 3; ni++)
#pragma unroll
        for (int q = 0; q < 4; q++) acc[ni][q] = 0.f;

    const float2* xtb = (const float2*)(g_xt + (size_t)b * HW * Cin) + lane;

    for (int k = 0; k < 9; k++) {
        int dy = k / 3 - 1;
        int dx = k % 3 - 1;
        int y = h + dy;
        bool yok = ((unsigned)y < (unsigned)H);

        __syncthreads();   // ssm/wsm free of previous tap's readers

        // stage B hi+lo: 2 * 64*24 floats, as float2 (stride 24 -> 40)
        for (int i = tid; i < 2 * Cin * NJ / 2; i += 256) {
            int half = (i >= Cin * NJ / 2);
            int ii = i - half * (Cin * NJ / 2);
            int c = ii / (NJ / 2);
            int j2 = ii - c * (NJ / 2);
            float2 w2 = ((const float2*)(g_woT + (size_t)half * 9 * Cin * NJ
                                         + (k * Cin + c) * NJ))[j2];
            uint32_t* dst = (half ? wsml : wsmh) + c * OWS + 2 * j2;
            dst[0] = __float_as_uint(w2.x);
            dst[1] = __float_as_uint(w2.y);
        }

        // stage A_hi: shifted row loads, lane = 2 channels, 16 px per warp
#pragma unroll 4
        for (int s = 0; s < 16; s++) {
            int px = px0 + s;
            int xw = wt + px + dx;
            bool ok = yok && ((unsigned)xw < (unsigned)W);
            float2 v = ok ? xtb[(ptrdiff_t)(y * W + xw) * (Cin / 2)]
                          : make_float2(0.f, 0.f);
            uint2 tv = make_uint2(f32_to_tf32(v.x), f32_to_tf32(v.y));
            *(uint2*)&ssm[px * SSTRIDE + 2 * lane] = tv;
        }
        __syncthreads();

        // pass 1: A_hi x (B_hi + B_lo)
#pragma unroll
        for (int kk = 0; kk < 8; kk++) {
            int k0 = kk << 3;
            uint32_t a[4];
            const uint32_t* ar = ssm + (px0 + g) * SSTRIDE + k0 + r;
            a[0] = ar[0];
            a[1] = ar[8 * SSTRIDE];
            a[2] = ar[4];
            a[3] = ar[8 * SSTRIDE + 4];
#pragma unroll
            for (int ni = 0; ni < 3; ni++) {
                const uint32_t* brh = wsmh + (k0 + r) * OWS + g + ni * 8;
                const uint32_t* brl = wsml + (k0 + r) * OWS + g + ni * 8;
                uint32_t bh[2] = { brh[0], brh[4 * OWS] };
                uint32_t bl[2] = { brl[0], brl[4 * OWS] };
                mma_tf32(acc[ni], a, bh);
                mma_tf32(acc[ni], a, bl);
            }
        }
        __syncthreads();   // pass-1 readers done with ssm

        // stage A_lo (reload v — L1 hit — and subtract hi)
#pragma unroll 4
        for (int s = 0; s < 16; s++) {
            int px = px0 + s;
            int xw = wt + px + dx;
            bool ok = yok && ((unsigned)xw < (unsigned)W);
            float2 v = ok ? xtb[(ptrdiff_t)(y * W + xw) * (Cin / 2)]
                          : make_float2(0.f, 0.f);
            float lox = v.x - __uint_as_float(f32_to_tf32(v.x));
            float loy = v.y - __uint_as_float(f32_to_tf32(v.y));
            uint2 tv = make_uint2(f32_to_tf32(lox), f32_to_tf32(loy));
            *(uint2*)&ssm[px * SSTRIDE + 2 * lane] = tv;
        }
        __syncthreads();

        // pass 2: A_lo x B_hi
#pragma unroll
        for (int kk = 0; kk < 8; kk++) {
            int k0 = kk << 3;
            uint32_t a[4];
            const uint32_t* ar = ssm + (px0 + g) * SSTRIDE + k0 + r;
            a[0] = ar[0];
            a[1] = ar[8 * SSTRIDE];
            a[2] = ar[4];
            a[3] = ar[8 * SSTRIDE + 4];
#pragma unroll
            for (int ni = 0; ni < 3; ni++) {
                const uint32_t* brh = wsmh + (k0 + r) * OWS + g + ni * 8;
                uint32_t bh[2] = { brh[0], brh[4 * OWS] };
                mma_tf32(acc[ni], a, bh);
            }
        }
    }

    // epilogue: j = ni*8 + 2r (+1); rows px0+g, px0+g+8; guard j < 18
#pragma unroll
    for (int ni = 0; ni < 3; ni++) {
        int j = ni * 8 + 2 * r;
        if (j < 18) {
            float* ob = g_offs + ((size_t)b * 18 + j) * HW + h * W + wt;
            float bj = b_off[j];
            ob[px0 + g]     = acc[ni][0] + bj;
            ob[px0 + g + 8] = acc[ni][2] + bj;
        }
        if (j + 1 < 18) {
            float* ob = g_offs + ((size_t)b * 18 + j + 1) * HW + h * W + wt;
            float bj = b_off[j + 1];
            ob[px0 + g]     = acc[ni][1] + bj;
            ob[px0 + g + 8] = acc[ni][3] + bj;
        }
    }
}

// ---------------------------------------------------------------------------
// Kernel 2: deform sampling (NHWC) + tf32 MMA (unchanged from R5 — protected)
// ---------------------------------------------------------------------------
struct __align__(16) SampleParam { int y0; int x0; float ly; float lx; };

#define SSM_U32 (MTILE * SSTRIDE)
#define WSM_U32 (Cin * WSTRIDE)
#define DSMEM_BYTES ((SSM_U32 + WSM_U32) * 4 + MTILE * 16)   // 55296 B

__global__ void __launch_bounds__(256, 4) deform_kernel(
    const float* __restrict__ b_def,
    float* __restrict__ out)
{
    extern __shared__ uint32_t dsm[];
    uint32_t* ssm = dsm;                        // [px][c] stride 68
    uint32_t* wsm = dsm + SSM_U32;              // [c][o]  stride 72
    SampleParam* sp = (SampleParam*)(dsm + SSM_U32 + WSM_U32);   // [px], one tap

    int tid = threadIdx.x;
    int bx = blockIdx.x;
    int wt = (bx & 1) << 7;
    int h = (bx >> 1) & (H - 1);
    int b = bx >> 9;

    const float* offb = g_offs + (size_t)b * 18 * HW + h * W + wt;

    if (tid < MTILE) {
        int px = tid;
        float offy = offb[0 * HW + px];
        float offx = offb[1 * HW + px];
        float ys = (float)(h - 1) + offy;
        float xs = (float)(wt + px - 1) + offx;
        float y0f = floorf(ys);
        float x0f = floorf(xs);
        SampleParam p;
        p.y0 = (int)y0f;
        p.x0 = (int)x0f;
        p.ly = ys - y0f;
        p.lx = xs - x0f;
        sp[px] = p;
    }

    int lane = tid & 31;
    int wid = tid >> 5;
    int warp_m = (wid & 3) << 5;
    int warp_n = (wid >> 2) << 5;
    int r = lane & 3;
    int g = lane >> 2;

    float acc[2][4][4];
#pragma unroll
    for (int mi = 0; mi < 2; mi++)
#pragma unroll
        for (int ni = 0; ni < 4; ni++)
#pragma unroll
            for (int q = 0; q < 4; q++) acc[mi][ni][q] = 0.f;

    const float2* xtb = (const float2*)(g_xt + (size_t)b * HW * Cin) + lane;
    int px0 = wid << 4;

    for (int k = 0; k < 9; k++) {
        __syncthreads();

        {
            const float4* src = (const float4*)(g_wT + (size_t)k * Cin * OUTC);
            for (int i = tid; i < Cin * OUTC / 4; i += 256) {
                int c = i >> 4;
                int q = i & 15;
                ((float4*)(wsm + c * WSTRIDE))[q] = src[i];
            }
        }

#pragma unroll 4
        for (int s = 0; s < 16; s++) {
            int px = px0 + s;
            SampleParam p = sp[px];
            float hy = 1.f - p.ly, hx = 1.f - p.lx;
            float w00 = hy * hx, w01 = hy * p.lx;
            float w10 = p.ly * hx, w11 = p.ly * p.lx;
            bool y0k = ((unsigned)p.y0 < (unsigned)H);
            bool y1k = ((unsigned)(p.y0 + 1) < (unsigned)H);
            bool x0k = ((unsigned)p.x0 < (unsigned)W);
            bool x1k = ((unsigned)(p.x0 + 1) < (unsigned)W);
            const float2* base = xtb + (ptrdiff_t)(p.y0 * W + p.x0) * (Cin / 2);
            float2 z = make_float2(0.f, 0.f);
            float2 v00 = (y0k && x0k) ? base[0] : z;
            float2 v01 = (y0k && x1k) ? base[Cin / 2] : z;
            float2 v10 = (y1k && x0k) ? base[(ptrdiff_t)W * (Cin / 2)] : z;
            float2 v11 = (y1k && x1k) ? base[(ptrdiff_t)(W + 1) * (Cin / 2)] : z;
            float vx = w00 * v00.x + w01 * v01.x + w10 * v10.x + w11 * v11.x;
            float vy = w00 * v00.y + w01 * v01.y + w10 * v10.y + w11 * v11.y;
            uint2 tv = make_uint2(f32_to_tf32(vx), f32_to_tf32(vy));
            *(uint2*)&ssm[px * SSTRIDE + 2 * lane] = tv;
        }
        __syncthreads();

        if (k < 8 && tid < MTILE) {
            int kn = k + 1;
            int px = tid;
            float offy = offb[(size_t)(2 * kn) * HW + px];
            float offx = offb[(size_t)(2 * kn + 1) * HW + px];
            float ys = (float)(h + (kn / 3) - 1) + offy;
            float xs = (float)(wt + px + (kn % 3) - 1) + offx;
            float y0f = floorf(ys);
            float x0f = floorf(xs);
            SampleParam p;
            p.y0 = (int)y0f;
            p.x0 = (int)x0f;
            p.ly = ys - y0f;
            p.lx = xs - x0f;
            sp[px] = p;
        }

#pragma unroll
        for (int kk = 0; kk < 8; kk++) {
            int k0 = kk << 3;
            uint32_t a[2][4];
#pragma unroll
            for (int mi = 0; mi < 2; mi++) {
                const uint32_t* ar = ssm + (warp_m + 16 * mi + g) * SSTRIDE + k0 + r;
                a[mi][0] = ar[0];
                a[mi][1] = ar[8 * SSTRIDE];
                a[mi][2] = ar[4];
                a[mi][3] = ar[8 * SSTRIDE + 4];
            }
            uint32_t bb[4][2];
            const uint32_t* br = wsm + (k0 + r) * WSTRIDE + warp_n + g;
#pragma unroll
            for (int ni = 0; ni < 4; ni++) {
                bb[ni][0] = br[ni * 8];
                bb[ni][1] = br[ni * 8 + 4 * WSTRIDE];
            }
#pragma unroll
            for (int mi = 0; mi < 2; mi++)
#pragma unroll
                for (int ni = 0; ni < 4; ni++)
                    mma_tf32(acc[mi][ni], a[mi], bb[ni]);
        }
    }

#pragma unroll
    for (int ni = 0; ni < 4; ni++) {
        int o = warp_n + ni * 8 + 2 * r;
        float bo0 = b_def[o];
        float bo1 = b_def[o + 1];
        float* ob0 = out + ((size_t)(b * OUTC + o)) * HW + h * W + wt;
        float* ob1 = ob0 + HW;
#pragma unroll
        for (int mi = 0; mi < 2; mi++) {
            int px = warp_m + mi * 16 + g;
            ob0[px]     = acc[mi][ni][0] + bo0;
            ob1[px]     = acc[mi][ni][1] + bo1;
            ob0[px + 8] = acc[mi][ni][2] + bo0;
            ob1[px + 8] = acc[mi][ni][3] + bo1;
        }
    }
}

// ---------------------------------------------------------------------------
extern "C" void kernel_launch(void* const* d_in, const int* in_sizes, int n_in,
                              void* d_out, int out_size)
{
    const float* x     = (const float*)d_in[0];
    const float* w_off = (const float*)d_in[1];
    const float* b_off = (const float*)d_in[2];
    const float* w_def = (const float*)d_in[3];
    const float* b_def = (const float*)d_in[4];
    float* out = (float*)d_out;

    cudaFuncSetAttribute(deform_kernel,
                         cudaFuncAttributeMaxDynamicSharedMemorySize, DSMEM_BYTES);
    cudaFuncSetAttribute(offsets_kernel,
                         cudaFuncAttributeMaxDynamicSharedMemorySize, OFF_DSMEM);

    transpose_wdef_kernel<<<(OUTC * Cin * 9 + 255) / 256, 256>>>(w_def);
    prep_woff_kernel<<<(9 * Cin * NJ + 255) / 256, 256>>>(w_off);
    transpose_x_kernel<<<Bsz * H * (W / 32), 256>>>(x);
    offsets_kernel<<<Bsz * H * (W / MTILE), 256, OFF_DSMEM>>>(b_off);
    deform_kernel<<<Bsz * H * (W / MTILE), 256, DSMEM_BYTES>>>(b_def, out);
}

// round 7
// speedup vs baseline: 1.4239x; 1.4239x over previous
#include <cuda_runtime.h>
#include <cuda_fp16.h>
#include <cstdint>

#define Bsz 4
#define Cin 64
#define OUTC 64
#define H 256
#define W 256
#define HW (H*W)

#define MTILE 128          // pixels per CTA (half row)
#define SH 72              // ssm/wsm stride in halves (64 + 8 pad) -> conflict-free
#define SH32 (SH/2)        // = 36 u32 per row

// Scratch (device globals — no allocation allowed)
__device__ float g_offs[(size_t)Bsz * 18 * HW];        // offset conv output (fp32 exact)
__device__ __half g_wh[9 * OUTC * Cin];                // w_def -> [k][o][c] fp16
__device__ float g_xt[(size_t)Bsz * HW * Cin];         // x transposed to NHWC (64MB)

// ---------------------------------------------------------------------------
// helpers
// ---------------------------------------------------------------------------
__device__ __forceinline__ void mma_f16(float* d, const uint32_t* a, const uint32_t* b) {
    asm volatile(
        "mma.sync.aligned.m16n8k16.row.col.f32.f16.f16.f32 "
        "{%0,%1,%2,%3}, {%4,%5,%6,%7}, {%8,%9}, {%0,%1,%2,%3};"
        : "+f"(d[0]), "+f"(d[1]), "+f"(d[2]), "+f"(d[3])
        : "r"(a[0]), "r"(a[1]), "r"(a[2]), "r"(a[3]),
          "r"(b[0]), "r"(b[1]));
}

// packed dual-FMA: d = a*b + d (elementwise on 2 floats) — exact fp32
__device__ __forceinline__ void ffma2(unsigned long long& d,
                                      unsigned long long a,
                                      unsigned long long b) {
    asm("fma.rn.f32x2 %0, %1, %2, %0;" : "+l"(d) : "l"(a), "l"(b));
}

__device__ __forceinline__ unsigned long long bcast2(float v) {
    unsigned long long r;
    asm("mov.b64 %0, {%1, %1};" : "=l"(r) : "f"(v));
    return r;
}

__device__ __forceinline__ void unpack2(unsigned long long v, float& lo, float& hi) {
    asm("mov.b64 {%0, %1}, %2;" : "=f"(lo), "=f"(hi) : "l"(v));
}

// ---------------------------------------------------------------------------
// Kernel 0a: w_def [o][c][ki][kj] -> g_wh[k][o][c] (fp16)
// ---------------------------------------------------------------------------
__global__ void prep_wdef_kernel(const float* __restrict__ w_def) {
    int idx = blockIdx.x * 256 + threadIdx.x;
    if (idx >= 9 * OUTC * Cin) return;
    int k = idx / (OUTC * Cin);
    int rem = idx - k * (OUTC * Cin);
    int o = rem / Cin;
    int c = rem - o * Cin;
    g_wh[idx] = __float2half_rn(w_def[(o * Cin + c) * 9 + k]);
}

// ---------------------------------------------------------------------------
// Kernel 0b: transpose x NCHW -> NHWC (g_xt)
// ---------------------------------------------------------------------------
__global__ void __launch_bounds__(256) transpose_x_kernel(const float* __restrict__ x) {
    __shared__ float t[Cin][33];
    int tid = threadIdx.x;
    int bx = blockIdx.x;
    int wt = (bx & 7) << 5;
    int h = (bx >> 3) & (H - 1);
    int b = bx >> 11;

    const float* xb = x + (size_t)b * Cin * HW + h * W + wt;
#pragma unroll
    for (int it = 0; it < 8; it++) {
        int c = it * 8 + (tid >> 5);
        int w = tid & 31;
        t[c][w] = xb[(size_t)c * HW + w];
    }
    __syncthreads();
    float* xo = g_xt + ((size_t)(b * H + h) * W + wt) * Cin;
#pragma unroll
    for (int it = 0; it < 8; it++) {
        int w = it * 4 + (tid >> 6);
        int c = tid & 63;
        xo[(size_t)w * Cin + c] = t[c][w];
    }
}

// ---------------------------------------------------------------------------
// Kernel 1: offset conv (exact fp32; FFMA2 + LDS.128 weights) — R5 proven
// ---------------------------------------------------------------------------
__global__ void __launch_bounds__(256) offsets_kernel(
    const float* __restrict__ x,
    const float* __restrict__ w_off,
    const float* __restrict__ b_off)
{
    __shared__ float wA[Cin * 9 * 20];

    int tid = threadIdx.x;
    for (int i = tid; i < Cin * 9 * 18; i += 256) {
        int j = i % 18;
        int ct = i / 18;
        wA[ct * 20 + j] = w_off[j * (Cin * 9) + ct];
    }
    for (int i = tid; i < Cin * 9; i += 256) {
        wA[i * 20 + 18] = 0.f;
        wA[i * 20 + 19] = 0.f;
    }
    __syncthreads();

    int w = tid;
    int h = blockIdx.x % H;
    int b = blockIdx.x / H;

    unsigned long long acc[9];
#pragma unroll
    for (int j = 0; j < 9; j++) {
        float2 bv = *(const float2*)&b_off[2 * j];
        asm("mov.b64 %0, {%1, %2};" : "=l"(acc[j]) : "f"(bv.x), "f"(bv.y));
    }

    const float* xb = x + (size_t)b * Cin * HW;
    bool hok[3] = { h > 0, true, h < H - 1 };
    bool wok[3] = { w > 0, true, w < W - 1 };

    for (int c = 0; c < Cin; c++) {
        const float* xc = xb + c * HW + h * W + w;
        float v[9];
#pragma unroll
        for (int dy = 0; dy < 3; dy++)
#pragma unroll
            for (int dx = 0; dx < 3; dx++) {
                int t = dy * 3 + dx;
                v[t] = (hok[dy] && wok[dx]) ? xc[(dy - 1) * W + (dx - 1)] : 0.f;
            }
#pragma unroll
        for (int t = 0; t < 9; t++) {
            unsigned long long vt2 = bcast2(v[t]);
            const float* wp = &wA[(c * 9 + t) * 20];
            ulonglong2 q0 = *(const ulonglong2*)(wp);
            ulonglong2 q1 = *(const ulonglong2*)(wp + 4);
            ulonglong2 q2 = *(const ulonglong2*)(wp + 8);
            ulonglong2 q3 = *(const ulonglong2*)(wp + 12);
            unsigned long long q4 = *(const unsigned long long*)(wp + 16);
            ffma2(acc[0], vt2, q0.x);
            ffma2(acc[1], vt2, q0.y);
            ffma2(acc[2], vt2, q1.x);
            ffma2(acc[3], vt2, q1.y);
            ffma2(acc[4], vt2, q2.x);
            ffma2(acc[5], vt2, q2.y);
            ffma2(acc[6], vt2, q3.x);
            ffma2(acc[7], vt2, q3.y);
            ffma2(acc[8], vt2, q4);
        }
    }

    float* ob = g_offs + ((size_t)b * 18) * HW + h * W + w;
#pragma unroll
    for (int j = 0; j < 9; j++) {
        float lo, hi;
        unpack2(acc[j], lo, hi);
        ob[(size_t)(2 * j) * HW] = lo;
        ob[(size_t)(2 * j + 1) * HW] = hi;
    }
}

// ---------------------------------------------------------------------------
// Kernel 2: deform sampling (NHWC) + fp16 m16n8k16 MMA (fp32 accum)
// ssm: fp16 [px][c] stride 72 halves; wsm: fp16 [o][c] stride 72 halves.
// Structure identical to R5 (proven): per-tap stage + single sp buffer
// prefetched during MMA phase.
// ---------------------------------------------------------------------------
struct __align__(16) SampleParam { int y0; int x0; float ly; float lx; };

#define SSM_U32 (MTILE * SH32)            // 4608 u32 = 18432 B
#define WSM_U32 (OUTC * SH32)             // 2304 u32 =  9216 B
#define DSMEM_BYTES ((SSM_U32 + WSM_U32) * 4 + MTILE * 16)   // 29696 B

__global__ void __launch_bounds__(256, 4) deform_kernel(
    const float* __restrict__ b_def,
    float* __restrict__ out)
{
    extern __shared__ uint32_t dsm[];
    uint32_t* ssm = dsm;                        // fp16 [px][c], u32 view
    uint32_t* wsm = dsm + SSM_U32;              // fp16 [o][c], u32 view
    SampleParam* sp = (SampleParam*)(dsm + SSM_U32 + WSM_U32);   // [px], one tap

    int tid = threadIdx.x;
    int bx = blockIdx.x;
    int wt = (bx & 1) << 7;
    int h = (bx >> 1) & (H - 1);
    int b = bx >> 9;

    const float* offb = g_offs + (size_t)b * 18 * HW + h * W + wt;

    // params for tap 0
    if (tid < MTILE) {
        int px = tid;
        float offy = offb[0 * HW + px];
        float offx = offb[1 * HW + px];
        float ys = (float)(h - 1) + offy;
        float xs = (float)(wt + px - 1) + offx;
        float y0f = floorf(ys);
        float x0f = floorf(xs);
        SampleParam p;
        p.y0 = (int)y0f;
        p.x0 = (int)x0f;
        p.ly = ys - y0f;
        p.lx = xs - x0f;
        sp[px] = p;
    }

    int lane = tid & 31;
    int wid = tid >> 5;
    int warp_m = (wid & 3) << 5;
    int warp_n = (wid >> 2) << 5;
    int r = lane & 3;
    int g = lane >> 2;

    float acc[2][4][4];
#pragma unroll
    for (int mi = 0; mi < 2; mi++)
#pragma unroll
        for (int ni = 0; ni < 4; ni++)
#pragma unroll
            for (int q = 0; q < 4; q++) acc[mi][ni][q] = 0.f;

    const float2* xtb = (const float2*)(g_xt + (size_t)b * HW * Cin) + lane;
    int px0 = wid << 4;

    for (int k = 0; k < 9; k++) {
        __syncthreads();   // ssm/wsm reusable; sp (this tap) visible

        // stage fp16 weights [o][c] for this tap: 4096 halves as 512 uint4
        {
            const uint4* src = (const uint4*)(g_wh + (size_t)k * OUTC * Cin);
            for (int i = tid; i < OUTC * Cin / 8; i += 256) {
                int o = i >> 3;
                int c8 = i & 7;
                *(uint4*)(wsm + o * SH32 + c8 * 4) = src[i];
            }
        }

        // coalesced bilinear sampling: warp covers 16 px, lane = 2 channels
#pragma unroll 4
        for (int s = 0; s < 16; s++) {
            int px = px0 + s;
            SampleParam p = sp[px];
            float hy = 1.f - p.ly, hx = 1.f - p.lx;
            float w00 = hy * hx, w01 = hy * p.lx;
            float w10 = p.ly * hx, w11 = p.ly * p.lx;
            bool y0k = ((unsigned)p.y0 < (unsigned)H);
            bool y1k = ((unsigned)(p.y0 + 1) < (unsigned)H);
            bool x0k = ((unsigned)p.x0 < (unsigned)W);
            bool x1k = ((unsigned)(p.x0 + 1) < (unsigned)W);
            const float2* base = xtb + (ptrdiff_t)(p.y0 * W + p.x0) * (Cin / 2);
            float2 z = make_float2(0.f, 0.f);
            float2 v00 = (y0k && x0k) ? base[0] : z;
            float2 v01 = (y0k && x1k) ? base[Cin / 2] : z;
            float2 v10 = (y1k && x0k) ? base[(ptrdiff_t)W * (Cin / 2)] : z;
            float2 v11 = (y1k && x1k) ? base[(ptrdiff_t)(W + 1) * (Cin / 2)] : z;
            float vx = w00 * v00.x + w01 * v01.x + w10 * v10.x + w11 * v11.x;
            float vy = w00 * v00.y + w01 * v01.y + w10 * v10.y + w11 * v11.y;
            uint32_t pv;   // lo = vx (ch 2*lane), hi = vy (ch 2*lane+1)
            asm("cvt.rn.f16x2.f32 %0, %1, %2;" : "=r"(pv) : "f"(vy), "f"(vx));
            ssm[px * SH32 + lane] = pv;
        }
        __syncthreads();   // ssm ready; sp readers (this tap) done

        // prefetch next tap's sampling params (overlaps MMA)
        if (k < 8 && tid < MTILE) {
            int kn = k + 1;
            int px = tid;
            float offy = offb[(size_t)(2 * kn) * HW + px];
            float offx = offb[(size_t)(2 * kn + 1) * HW + px];
            float ys = (float)(h + (kn / 3) - 1) + offy;
            float xs = (float)(wt + px + (kn % 3) - 1) + offx;
            float y0f = floorf(ys);
            float x0f = floorf(xs);
            SampleParam p;
            p.y0 = (int)y0f;
            p.x0 = (int)x0f;
            p.ly = ys - y0f;
            p.lx = xs - x0f;
            sp[px] = p;
        }

        // MMA: 4 k-steps of m16n8k16
#pragma unroll
        for (int kk = 0; kk < 4; kk++) {
            int kb = kk << 3;          // u32 offset within row (16 halves)
            uint32_t a[2][4];
#pragma unroll
            for (int mi = 0; mi < 2; mi++) {
                const uint32_t* ar = ssm + (warp_m + 16 * mi + g) * SH32 + kb + r;
                a[mi][0] = ar[0];                  // (g,   2r..2r+1)
                a[mi][1] = ar[8 * SH32];           // (g+8, 2r..)
                a[mi][2] = ar[4];                  // (g,   2r+8..)
                a[mi][3] = ar[8 * SH32 + 4];       // (g+8, 2r+8..)
            }
            uint32_t bb[4][2];
#pragma unroll
            for (int ni = 0; ni < 4; ni++) {
                const uint32_t* br = wsm + (warp_n + ni * 8 + g) * SH32 + kb + r;
                bb[ni][0] = br[0];                 // (2r..,   n=g)
                bb[ni][1] = br[4];                 // (2r+8.., n=g)
            }
#pragma unroll
            for (int mi = 0; mi < 2; mi++)
#pragma unroll
                for (int ni = 0; ni < 4; ni++)
                    mma_f16(acc[mi][ni], a[mi], bb[ni]);
        }
    }

    // ---- epilogue: bias + direct stores (NCHW out) ----
#pragma unroll
    for (int ni = 0; ni < 4; ni++) {
        int o = warp_n + ni * 8 + 2 * r;
        float bo0 = b_def[o];
        float bo1 = b_def[o + 1];
        float* ob0 = out + ((size_t)(b * OUTC + o)) * HW + h * W + wt;
        float* ob1 = ob0 + HW;
#pragma unroll
        for (int mi = 0; mi < 2; mi++) {
            int px = warp_m + mi * 16 + g;
            ob0[px]     = acc[mi][ni][0] + bo0;
            ob1[px]     = acc[mi][ni][1] + bo1;
            ob0[px + 8] = acc[mi][ni][2] + bo0;
            ob1[px + 8] = acc[mi][ni][3] + bo1;
        }
    }
}

// ---------------------------------------------------------------------------
extern "C" void kernel_launch(void* const* d_in, const int* in_sizes, int n_in,
                              void* d_out, int out_size)
{
    const float* x     = (const float*)d_in[0];
    const float* w_off = (const float*)d_in[1];
    const float* b_off = (const float*)d_in[2];
    const float* w_def = (const float*)d_in[3];
    const float* b_def = (const float*)d_in[4];
    float* out = (float*)d_out;

    cudaFuncSetAttribute(deform_kernel,
                         cudaFuncAttributeMaxDynamicSharedMemorySize, DSMEM_BYTES);

    prep_wdef_kernel<<<(9 * OUTC * Cin + 255) / 256, 256>>>(w_def);
    transpose_x_kernel<<<Bsz * H * (W / 32), 256>>>(x);
    offsets_kernel<<<Bsz * H, 256>>>(x, w_off, b_off);
    deform_kernel<<<Bsz * H * (W / MTILE), 256, DSMEM_BYTES>>>(b_def, out);
}

// round 8
// speedup vs baseline: 1.5087x; 1.0596x over previous
#include <cuda_runtime.h>
#include <cuda_fp16.h>
#include <cstdint>

#define Bsz 4
#define Cin 64
#define OUTC 64
#define H 256
#define W 256
#define HW (H*W)

#define MTILE 128          // pixels per CTA (half row)
#define SH 72              // ssm/wsm stride in halves (64 + 8 pad) -> conflict-free
#define SH32 (SH/2)        // = 36 u32 per row

// Scratch (device globals — no allocation allowed)
__device__ float g_offs[(size_t)Bsz * 18 * HW];        // offset conv output (fp32 exact)
__device__ __half g_wh[9 * OUTC * Cin];                // w_def -> [k][o][c] fp16
__device__ float g_xt[(size_t)Bsz * HW * Cin];         // x transposed to NHWC (64MB)

// ---------------------------------------------------------------------------
// helpers
// ---------------------------------------------------------------------------
__device__ __forceinline__ void mma_f16(float* d, const uint32_t* a, const uint32_t* b) {
    asm volatile(
        "mma.sync.aligned.m16n8k16.row.col.f32.f16.f16.f32 "
        "{%0,%1,%2,%3}, {%4,%5,%6,%7}, {%8,%9}, {%0,%1,%2,%3};"
        : "+f"(d[0]), "+f"(d[1]), "+f"(d[2]), "+f"(d[3])
        : "r"(a[0]), "r"(a[1]), "r"(a[2]), "r"(a[3]),
          "r"(b[0]), "r"(b[1]));
}

// packed dual-FMA: d = a*b + d (elementwise on 2 floats) — exact fp32
__device__ __forceinline__ void ffma2(unsigned long long& d,
                                      unsigned long long a,
                                      unsigned long long b) {
    asm("fma.rn.f32x2 %0, %1, %2, %0;" : "+l"(d) : "l"(a), "l"(b));
}

__device__ __forceinline__ unsigned long long bcast2(float v) {
    unsigned long long r;
    asm("mov.b64 %0, {%1, %1};" : "=l"(r) : "f"(v));
    return r;
}

__device__ __forceinline__ void unpack2(unsigned long long v, float& lo, float& hi) {
    asm("mov.b64 {%0, %1}, %2;" : "=f"(lo), "=f"(hi) : "l"(v));
}

// ---------------------------------------------------------------------------
// Kernel 0a: w_def [o][c][ki][kj] -> g_wh[k][o][c] (fp16)
// ---------------------------------------------------------------------------
__global__ void prep_wdef_kernel(const float* __restrict__ w_def) {
    int idx = blockIdx.x * 256 + threadIdx.x;
    if (idx >= 9 * OUTC * Cin) return;
    int k = idx / (OUTC * Cin);
    int rem = idx - k * (OUTC * Cin);
    int o = rem / Cin;
    int c = rem - o * Cin;
    g_wh[idx] = __float2half_rn(w_def[(o * Cin + c) * 9 + k]);
}

// ---------------------------------------------------------------------------
// Kernel 0b: transpose x NCHW -> NHWC (g_xt)
// ---------------------------------------------------------------------------
__global__ void __launch_bounds__(256) transpose_x_kernel(const float* __restrict__ x) {
    __shared__ float t[Cin][33];
    int tid = threadIdx.x;
    int bx = blockIdx.x;
    int wt = (bx & 7) << 5;
    int h = (bx >> 3) & (H - 1);
    int b = bx >> 11;

    const float* xb = x + (size_t)b * Cin * HW + h * W + wt;
#pragma unroll
    for (int it = 0; it < 8; it++) {
        int c = it * 8 + (tid >> 5);
        int w = tid & 31;
        t[c][w] = xb[(size_t)c * HW + w];
    }
    __syncthreads();
    float* xo = g_xt + ((size_t)(b * H + h) * W + wt) * Cin;
#pragma unroll
    for (int it = 0; it < 8; it++) {
        int w = it * 4 + (tid >> 6);
        int c = tid & 63;
        xo[(size_t)w * Cin + c] = t[c][w];
    }
}

// ---------------------------------------------------------------------------
// Kernel 1: offset conv (exact fp32; FFMA2 + LDS.128 weights; c unrolled x2
// for MLP=18 to cover L2 latency)
// ---------------------------------------------------------------------------
__global__ void __launch_bounds__(256) offsets_kernel(
    const float* __restrict__ x,
    const float* __restrict__ w_off,
    const float* __restrict__ b_off)
{
    __shared__ float wA[Cin * 9 * 20];

    int tid = threadIdx.x;
    for (int i = tid; i < Cin * 9 * 18; i += 256) {
        int j = i % 18;
        int ct = i / 18;
        wA[ct * 20 + j] = w_off[j * (Cin * 9) + ct];
    }
    for (int i = tid; i < Cin * 9; i += 256) {
        wA[i * 20 + 18] = 0.f;
        wA[i * 20 + 19] = 0.f;
    }
    __syncthreads();

    int w = tid;
    int h = blockIdx.x % H;
    int b = blockIdx.x / H;

    unsigned long long acc[9];
#pragma unroll
    for (int j = 0; j < 9; j++) {
        float2 bv = *(const float2*)&b_off[2 * j];
        asm("mov.b64 %0, {%1, %2};" : "=l"(acc[j]) : "f"(bv.x), "f"(bv.y));
    }

    const float* xb = x + (size_t)b * Cin * HW;
    bool hok[3] = { h > 0, true, h < H - 1 };
    bool wok[3] = { w > 0, true, w < W - 1 };

    for (int c = 0; c < Cin; c += 2) {
        const float* xc0 = xb + c * HW + h * W + w;
        const float* xc1 = xc0 + HW;
        float v0[9], v1[9];
        // batch all 18 loads first (MLP=18)
#pragma unroll
        for (int dy = 0; dy < 3; dy++)
#pragma unroll
            for (int dx = 0; dx < 3; dx++) {
                int t = dy * 3 + dx;
                bool ok = hok[dy] && wok[dx];
                ptrdiff_t off = (ptrdiff_t)(dy - 1) * W + (dx - 1);
                v0[t] = ok ? xc0[off] : 0.f;
                v1[t] = ok ? xc1[off] : 0.f;
            }
#pragma unroll
        for (int t = 0; t < 9; t++) {
            unsigned long long vt2 = bcast2(v0[t]);
            const float* wp = &wA[(c * 9 + t) * 20];
            ulonglong2 q0 = *(const ulonglong2*)(wp);
            ulonglong2 q1 = *(const ulonglong2*)(wp + 4);
            ulonglong2 q2 = *(const ulonglong2*)(wp + 8);
            ulonglong2 q3 = *(const ulonglong2*)(wp + 12);
            unsigned long long q4 = *(const unsigned long long*)(wp + 16);
            ffma2(acc[0], vt2, q0.x);
            ffma2(acc[1], vt2, q0.y);
            ffma2(acc[2], vt2, q1.x);
            ffma2(acc[3], vt2, q1.y);
            ffma2(acc[4], vt2, q2.x);
            ffma2(acc[5], vt2, q2.y);
            ffma2(acc[6], vt2, q3.x);
            ffma2(acc[7], vt2, q3.y);
            ffma2(acc[8], vt2, q4);
        }
#pragma unroll
        for (int t = 0; t < 9; t++) {
            unsigned long long vt2 = bcast2(v1[t]);
            const float* wp = &wA[((c + 1) * 9 + t) * 20];
            ulonglong2 q0 = *(const ulonglong2*)(wp);
            ulonglong2 q1 = *(const ulonglong2*)(wp + 4);
            ulonglong2 q2 = *(const ulonglong2*)(wp + 8);
            ulonglong2 q3 = *(const ulonglong2*)(wp + 12);
            unsigned long long q4 = *(const unsigned long long*)(wp + 16);
            ffma2(acc[0], vt2, q0.x);
            ffma2(acc[1], vt2, q0.y);
            ffma2(acc[2], vt2, q1.x);
            ffma2(acc[3], vt2, q1.y);
            ffma2(acc[4], vt2, q2.x);
            ffma2(acc[5], vt2, q2.y);
            ffma2(acc[6], vt2, q3.x);
            ffma2(acc[7], vt2, q3.y);
            ffma2(acc[8], vt2, q4);
        }
    }

    float* ob = g_offs + ((size_t)b * 18) * HW + h * W + w;
#pragma unroll
    for (int j = 0; j < 9; j++) {
        float lo, hi;
        unpack2(acc[j], lo, hi);
        ob[(size_t)(2 * j) * HW] = lo;
        ob[(size_t)(2 * j + 1) * HW] = hi;
    }
}

// ---------------------------------------------------------------------------
// Kernel 2: deform sampling (NHWC, float4/2-samples-per-warp) + fp16 MMA
// ---------------------------------------------------------------------------
struct __align__(16) SampleParam { int y0; int x0; float ly; float lx; };

#define SSM_U32 (MTILE * SH32)            // 4608 u32 = 18432 B
#define WSM_U32 (OUTC * SH32)             // 2304 u32 =  9216 B
#define DSMEM_BYTES ((SSM_U32 + WSM_U32) * 4 + MTILE * 16)   // 29696 B

__global__ void __launch_bounds__(256, 4) deform_kernel(
    const float* __restrict__ b_def,
    float* __restrict__ out)
{
    extern __shared__ uint32_t dsm[];
    uint32_t* ssm = dsm;                        // fp16 [px][c], u32 view
    uint32_t* wsm = dsm + SSM_U32;              // fp16 [o][c], u32 view
    SampleParam* sp = (SampleParam*)(dsm + SSM_U32 + WSM_U32);   // [px], one tap

    int tid = threadIdx.x;
    int bx = blockIdx.x;
    int wt = (bx & 1) << 7;
    int h = (bx >> 1) & (H - 1);
    int b = bx >> 9;

    const float* offb = g_offs + (size_t)b * 18 * HW + h * W + wt;

    // params for tap 0
    if (tid < MTILE) {
        int px = tid;
        float offy = offb[0 * HW + px];
        float offx = offb[1 * HW + px];
        float ys = (float)(h - 1) + offy;
        float xs = (float)(wt + px - 1) + offx;
        float y0f = floorf(ys);
        float x0f = floorf(xs);
        SampleParam p;
        p.y0 = (int)y0f;
        p.x0 = (int)x0f;
        p.ly = ys - y0f;
        p.lx = xs - x0f;
        sp[px] = p;
    }

    int lane = tid & 31;
    int wid = tid >> 5;
    int warp_m = (wid & 3) << 5;
    int warp_n = (wid >> 2) << 5;
    int r = lane & 3;
    int g = lane >> 2;

    float acc[2][4][4];
#pragma unroll
    for (int mi = 0; mi < 2; mi++)
#pragma unroll
        for (int ni = 0; ni < 4; ni++)
#pragma unroll
            for (int q = 0; q < 4; q++) acc[mi][ni][q] = 0.f;

    int half = lane >> 4;              // which of 2 samples per iteration
    int cl = lane & 15;                // channel quad: 4*cl .. 4*cl+3
    const float4* xtb4 = (const float4*)(g_xt + (size_t)b * HW * Cin) + cl;
    int px0 = wid << 4;

    for (int k = 0; k < 9; k++) {
        __syncthreads();   // ssm/wsm reusable; sp (this tap) visible

        // stage fp16 weights [o][c] for this tap
        {
            const uint4* src = (const uint4*)(g_wh + (size_t)k * OUTC * Cin);
            for (int i = tid; i < OUTC * Cin / 8; i += 256) {
                int o = i >> 3;
                int c8 = i & 7;
                *(uint4*)(wsm + o * SH32 + c8 * 4) = src[i];
            }
        }

        // gather: 8 iterations, 2 samples per warp, lane = 4 channels (LDG.128)
#pragma unroll 4
        for (int s = 0; s < 8; s++) {
            int px = px0 + 2 * s + half;
            SampleParam p = sp[px];
            float hy = 1.f - p.ly, hx = 1.f - p.lx;
            float w00 = hy * hx, w01 = hy * p.lx;
            float w10 = p.ly * hx, w11 = p.ly * p.lx;
            bool y0k = ((unsigned)p.y0 < (unsigned)H);
            bool y1k = ((unsigned)(p.y0 + 1) < (unsigned)H);
            bool x0k = ((unsigned)p.x0 < (unsigned)W);
            bool x1k = ((unsigned)(p.x0 + 1) < (unsigned)W);
            const float4* base = xtb4 + (ptrdiff_t)(p.y0 * W + p.x0) * (Cin / 4);
            float4 z = make_float4(0.f, 0.f, 0.f, 0.f);
            float4 v00 = (y0k && x0k) ? base[0] : z;
            float4 v01 = (y0k && x1k) ? base[Cin / 4] : z;
            float4 v10 = (y1k && x0k) ? base[(ptrdiff_t)W * (Cin / 4)] : z;
            float4 v11 = (y1k && x1k) ? base[(ptrdiff_t)(W + 1) * (Cin / 4)] : z;
            float rx = w00 * v00.x + w01 * v01.x + w10 * v10.x + w11 * v11.x;
            float ry = w00 * v00.y + w01 * v01.y + w10 * v10.y + w11 * v11.y;
            float rz = w00 * v00.z + w01 * v01.z + w10 * v10.z + w11 * v11.z;
            float rw = w00 * v00.w + w01 * v01.w + w10 * v10.w + w11 * v11.w;
            uint2 pv;
            asm("cvt.rn.f16x2.f32 %0, %1, %2;" : "=r"(pv.x) : "f"(ry), "f"(rx));
            asm("cvt.rn.f16x2.f32 %0, %1, %2;" : "=r"(pv.y) : "f"(rw), "f"(rz));
            *(uint2*)&ssm[px * SH32 + 2 * cl] = pv;
        }
        __syncthreads();   // ssm ready; sp readers (this tap) done

        // prefetch next tap's sampling params (overlaps MMA)
        if (k < 8 && tid < MTILE) {
            int kn = k + 1;
            int px = tid;
            float offy = offb[(size_t)(2 * kn) * HW + px];
            float offx = offb[(size_t)(2 * kn + 1) * HW + px];
            float ys = (float)(h + (kn / 3) - 1) + offy;
            float xs = (float)(wt + px + (kn % 3) - 1) + offx;
            float y0f = floorf(ys);
            float x0f = floorf(xs);
            SampleParam p;
            p.y0 = (int)y0f;
            p.x0 = (int)x0f;
            p.ly = ys - y0f;
            p.lx = xs - x0f;
            sp[px] = p;
        }

        // MMA: 4 k-steps of m16n8k16
#pragma unroll
        for (int kk = 0; kk < 4; kk++) {
            int kb = kk << 3;
            uint32_t a[2][4];
#pragma unroll
            for (int mi = 0; mi < 2; mi++) {
                const uint32_t* ar = ssm + (warp_m + 16 * mi + g) * SH32 + kb + r;
                a[mi][0] = ar[0];
                a[mi][1] = ar[8 * SH32];
                a[mi][2] = ar[4];
                a[mi][3] = ar[8 * SH32 + 4];
            }
            uint32_t bb[4][2];
#pragma unroll
            for (int ni = 0; ni < 4; ni++) {
                const uint32_t* br = wsm + (warp_n + ni * 8 + g) * SH32 + kb + r;
                bb[ni][0] = br[0];
                bb[ni][1] = br[4];
            }
#pragma unroll
            for (int mi = 0; mi < 2; mi++)
#pragma unroll
                for (int ni = 0; ni < 4; ni++)
                    mma_f16(acc[mi][ni], a[mi], bb[ni]);
        }
    }

    // ---- epilogue: bias + direct stores (NCHW out) ----
#pragma unroll
    for (int ni = 0; ni < 4; ni++) {
        int o = warp_n + ni * 8 + 2 * r;
        float bo0 = b_def[o];
        float bo1 = b_def[o + 1];
        float* ob0 = out + ((size_t)(b * OUTC + o)) * HW + h * W + wt;
        float* ob1 = ob0 + HW;
#pragma unroll
        for (int mi = 0; mi < 2; mi++) {
            int px = warp_m + mi * 16 + g;
            ob0[px]     = acc[mi][ni][0] + bo0;
            ob1[px]     = acc[mi][ni][1] + bo1;
            ob0[px + 8] = acc[mi][ni][2] + bo0;
            ob1[px + 8] = acc[mi][ni][3] + bo1;
        }
    }
}

// ---------------------------------------------------------------------------
extern "C" void kernel_launch(void* const* d_in, const int* in_sizes, int n_in,
                              void* d_out, int out_size)
{
    const float* x     = (const float*)d_in[0];
    const float* w_off = (const float*)d_in[1];
    const float* b_off = (const float*)d_in[2];
    const float* w_def = (const float*)d_in[3];
    const float* b_def = (const float*)d_in[4];
    float* out = (float*)d_out;

    cudaFuncSetAttribute(deform_kernel,
                         cudaFuncAttributeMaxDynamicSharedMemorySize, DSMEM_BYTES);

    prep_wdef_kernel<<<(9 * OUTC * Cin + 255) / 256, 256>>>(w_def);
    transpose_x_kernel<<<Bsz * H * (W / 32), 256>>>(x);
    offsets_kernel<<<Bsz * H, 256>>>(x, w_off, b_off);
    deform_kernel<<<Bsz * H * (W / MTILE), 256, DSMEM_BYTES>>>(b_def, out);
}

// round 9
// speedup vs baseline: 1.8974x; 1.2577x over previous
#include <cuda_runtime.h>
#include <cuda_fp16.h>
#include <cstdint>

#define Bsz 4
#define Cin 64
#define OUTC 64
#define H 256
#define W 256
#define HW (H*W)

#define MTILE 128          // pixels per CTA (half row)
#define SH 72              // ssm/wsm stride in halves (64 + 8 pad) -> conflict-free
#define SH32 (SH/2)        // = 36 u32 per row

#define OJ 24              // offset channels 18 padded to 24

// Scratch (device globals — no allocation allowed)
__device__ float g_offs[(size_t)Bsz * 18 * HW];        // offset conv output (fp32-accurate)
__device__ __half g_wh[9 * OUTC * Cin];                // w_def -> [k][o][c] fp16
__device__ float g_xt[(size_t)Bsz * HW * Cin];         // x transposed to NHWC (64MB)
__device__ __half g_wo_hi[9 * OJ * Cin];               // w_off split hi [k][j][c]
__device__ __half g_wo_lo[9 * OJ * Cin];               // w_off split lo [k][j][c]

// ---------------------------------------------------------------------------
// helpers
// ---------------------------------------------------------------------------
__device__ __forceinline__ void mma_f16(float* d, const uint32_t* a, const uint32_t* b) {
    asm volatile(
        "mma.sync.aligned.m16n8k16.row.col.f32.f16.f16.f32 "
        "{%0,%1,%2,%3}, {%4,%5,%6,%7}, {%8,%9}, {%0,%1,%2,%3};"
        : "+f"(d[0]), "+f"(d[1]), "+f"(d[2]), "+f"(d[3])
        : "r"(a[0]), "r"(a[1]), "r"(a[2]), "r"(a[3]),
          "r"(b[0]), "r"(b[1]));
}

__device__ __forceinline__ uint32_t pack_f16x2(float lo, float hi) {
    uint32_t r;
    asm("cvt.rn.f16x2.f32 %0, %1, %2;" : "=r"(r) : "f"(hi), "f"(lo));
    return r;
}

// ---------------------------------------------------------------------------
// Kernel 0a: w_def [o][c][ki][kj] -> g_wh[k][o][c] (fp16)
// ---------------------------------------------------------------------------
__global__ void prep_wdef_kernel(const float* __restrict__ w_def) {
    int idx = blockIdx.x * 256 + threadIdx.x;
    if (idx >= 9 * OUTC * Cin) return;
    int k = idx / (OUTC * Cin);
    int rem = idx - k * (OUTC * Cin);
    int o = rem / Cin;
    int c = rem - o * Cin;
    g_wh[idx] = __float2half_rn(w_def[(o * Cin + c) * 9 + k]);
}

// ---------------------------------------------------------------------------
// Kernel 0b: w_off [j][c][ki][kj] -> g_wo_{hi,lo}[k][j][c] fp16 split
// ---------------------------------------------------------------------------
__global__ void prep_woff_kernel(const float* __restrict__ w_off) {
    int idx = blockIdx.x * 256 + threadIdx.x;      // 9*24*64 = 13824
    if (idx >= 9 * OJ * Cin) return;
    int k = idx / (OJ * Cin);
    int rem = idx - k * (OJ * Cin);
    int j = rem / Cin;
    int c = rem - j * Cin;
    float v = (j < 18) ? w_off[((size_t)j * Cin + c) * 9 + k] : 0.f;
    __half hi = __float2half_rn(v);
    float lo = v - __half2float(hi);
    g_wo_hi[idx] = hi;
    g_wo_lo[idx] = __float2half_rn(lo);
}

// ---------------------------------------------------------------------------
// Kernel 0c: transpose x NCHW -> NHWC (g_xt)
// ---------------------------------------------------------------------------
__global__ void __launch_bounds__(256) transpose_x_kernel(const float* __restrict__ x) {
    __shared__ float t[Cin][33];
    int tid = threadIdx.x;
    int bx = blockIdx.x;
    int wt = (bx & 7) << 5;
    int h = (bx >> 3) & (H - 1);
    int b = bx >> 11;

    const float* xb = x + (size_t)b * Cin * HW + h * W + wt;
#pragma unroll
    for (int it = 0; it < 8; it++) {
        int c = it * 8 + (tid >> 5);
        int w = tid & 31;
        t[c][w] = xb[(size_t)c * HW + w];
    }
    __syncthreads();
    float* xo = g_xt + ((size_t)(b * H + h) * W + wt) * Cin;
#pragma unroll
    for (int it = 0; it < 8; it++) {
        int w = it * 4 + (tid >> 6);
        int c = tid & 63;
        xo[(size_t)w * Cin + c] = t[c][w];
    }
}

// ---------------------------------------------------------------------------
// Kernel 1: offsets conv via fp16 split-precision MMA (fp32-accurate).
// D = Ah*Bh + Ah*Bl + Al*Bh; dropped Al*Bl ~ 2^-22 -> offsets exact to ~1e-6.
// CTA: 128 px x 24(18) outputs; per tap: stage A hi+lo (one float4 row load,
// no bilinear), stage B hi+lo (fp16, 3.4KB), 4 k-steps x 3 n-tiles x 3 MMA.
// ---------------------------------------------------------------------------
#define OFF_SSMH_U32 (MTILE * SH32)                 // 4608
#define OFF_WSM_U32  (OJ * SH32)                    // 864
#define OFF_DSMEM ((2 * OFF_SSMH_U32 + 2 * OFF_WSM_U32) * 4)   // 43776 B

__global__ void __launch_bounds__(256, 4) offsets_kernel(
    const float* __restrict__ b_off)
{
    extern __shared__ uint32_t dsm[];
    uint32_t* ssm_h = dsm;                              // fp16 [px][c] hi
    uint32_t* ssm_l = ssm_h + OFF_SSMH_U32;             // fp16 [px][c] lo
    uint32_t* wsm_h = ssm_l + OFF_SSMH_U32;             // fp16 [j][c] hi
    uint32_t* wsm_l = wsm_h + OFF_WSM_U32;              // fp16 [j][c] lo

    int tid = threadIdx.x;
    int bx = blockIdx.x;
    int wt = (bx & 1) << 7;
    int h = (bx >> 1) & (H - 1);
    int b = bx >> 9;

    int lane = tid & 31;
    int wid = tid >> 5;
    int r = lane & 3;
    int g = lane >> 2;
    int half_id = lane >> 4;           // which of 2 samples per iter
    int cl = lane & 15;                // channel quad
    int px0 = wid << 4;                // warp's 16-px m-tile

    float acc[3][4];
#pragma unroll
    for (int ni = 0; ni < 3; ni++)
#pragma unroll
        for (int q = 0; q < 4; q++) acc[ni][q] = 0.f;

    const float4* xtb4 = (const float4*)(g_xt + (size_t)b * HW * Cin) + cl;

    for (int k = 0; k < 9; k++) {
        int dy = k / 3 - 1;
        int dx = k % 3 - 1;
        int y = h + dy;
        bool yok = ((unsigned)y < (unsigned)H);

        __syncthreads();   // ssm/wsm free of previous tap's readers

        // stage B hi+lo: 2 x 192 uint4
        {
            const uint4* sh = (const uint4*)(g_wo_hi + (size_t)k * OJ * Cin);
            const uint4* sl = (const uint4*)(g_wo_lo + (size_t)k * OJ * Cin);
            for (int i = tid; i < 2 * OJ * Cin / 8; i += 256) {
                int hf = (i >= OJ * Cin / 8);
                int ii = i - hf * (OJ * Cin / 8);
                int j = ii >> 3;
                int c8 = ii & 7;
                uint4 v = hf ? sl[ii] : sh[ii];
                *(uint4*)((hf ? wsm_l : wsm_h) + j * SH32 + c8 * 4) = v;
            }
        }

        // stage A hi+lo: 8 iters, 2 samples/warp, lane = 4 channels (LDG.128)
#pragma unroll 4
        for (int s = 0; s < 8; s++) {
            int px = px0 + 2 * s + half_id;
            int xw = wt + px + dx;
            bool ok = yok && ((unsigned)xw < (unsigned)W);
            float4 v = ok ? xtb4[(ptrdiff_t)(y * W + xw) * (Cin / 4)]
                          : make_float4(0.f, 0.f, 0.f, 0.f);
            __half ax = __float2half_rn(v.x);
            __half ay = __float2half_rn(v.y);
            __half az = __float2half_rn(v.z);
            __half aw = __float2half_rn(v.w);
            __half2 p0 = __halves2half2(ax, ay);
            __half2 p1 = __halves2half2(az, aw);
            uint2 ph = make_uint2(*(uint32_t*)&p0, *(uint32_t*)&p1);
            float lx = v.x - __half2float(ax);
            float ly = v.y - __half2float(ay);
            float lz = v.z - __half2float(az);
            float lw = v.w - __half2float(aw);
            uint2 pl = make_uint2(pack_f16x2(lx, ly), pack_f16x2(lz, lw));
            *(uint2*)&ssm_h[px * SH32 + 2 * cl] = ph;
            *(uint2*)&ssm_l[px * SH32 + 2 * cl] = pl;
        }
        __syncthreads();

        // MMA: 4 k-steps x 3 n-tiles x (Ah*Bh + Ah*Bl + Al*Bh)
#pragma unroll
        for (int kk = 0; kk < 4; kk++) {
            int kb = kk << 3;
            uint32_t ah[4], al[4];
            const uint32_t* arh = ssm_h + (px0 + g) * SH32 + kb + r;
            const uint32_t* arl = ssm_l + (px0 + g) * SH32 + kb + r;
            ah[0] = arh[0];
            ah[1] = arh[8 * SH32];
            ah[2] = arh[4];
            ah[3] = arh[8 * SH32 + 4];
            al[0] = arl[0];
            al[1] = arl[8 * SH32];
            al[2] = arl[4];
            al[3] = arl[8 * SH32 + 4];
#pragma unroll
            for (int ni = 0; ni < 3; ni++) {
                const uint32_t* brh = wsm_h + (ni * 8 + g) * SH32 + kb + r;
                const uint32_t* brl = wsm_l + (ni * 8 + g) * SH32 + kb + r;
                uint32_t bh[2] = { brh[0], brh[4] };
                uint32_t bl[2] = { brl[0], brl[4] };
                mma_f16(acc[ni], ah, bh);
                mma_f16(acc[ni], ah, bl);
                mma_f16(acc[ni], al, bh);
            }
        }
    }

    // epilogue: j = ni*8 + 2r (+1); rows px0+g, px0+g+8; guard j < 18
#pragma unroll
    for (int ni = 0; ni < 3; ni++) {
        int j = ni * 8 + 2 * r;
        if (j < 18) {
            float* ob = g_offs + ((size_t)b * 18 + j) * HW + h * W + wt;
            float bj = b_off[j];
            ob[px0 + g]     = acc[ni][0] + bj;
            ob[px0 + g + 8] = acc[ni][2] + bj;
        }
        if (j + 1 < 18) {
            float* ob = g_offs + ((size_t)b * 18 + j + 1) * HW + h * W + wt;
            float bj = b_off[j + 1];
            ob[px0 + g]     = acc[ni][1] + bj;
            ob[px0 + g + 8] = acc[ni][3] + bj;
        }
    }
}

// ---------------------------------------------------------------------------
// Kernel 2: deform sampling (NHWC, float4/2-samples-per-warp) + fp16 MMA
// (unchanged from R8 — protected win)
// ---------------------------------------------------------------------------
struct __align__(16) SampleParam { int y0; int x0; float ly; float lx; };

#define SSM_U32 (MTILE * SH32)            // 4608 u32 = 18432 B
#define WSM_U32 (OUTC * SH32)             // 2304 u32 =  9216 B
#define DSMEM_BYTES ((SSM_U32 + WSM_U32) * 4 + MTILE * 16)   // 29696 B

__global__ void __launch_bounds__(256, 4) deform_kernel(
    const float* __restrict__ b_def,
    float* __restrict__ out)
{
    extern __shared__ uint32_t dsm[];
    uint32_t* ssm = dsm;                        // fp16 [px][c], u32 view
    uint32_t* wsm = dsm + SSM_U32;              // fp16 [o][c], u32 view
    SampleParam* sp = (SampleParam*)(dsm + SSM_U32 + WSM_U32);   // [px], one tap

    int tid = threadIdx.x;
    int bx = blockIdx.x;
    int wt = (bx & 1) << 7;
    int h = (bx >> 1) & (H - 1);
    int b = bx >> 9;

    const float* offb = g_offs + (size_t)b * 18 * HW + h * W + wt;

    if (tid < MTILE) {
        int px = tid;
        float offy = offb[0 * HW + px];
        float offx = offb[1 * HW + px];
        float ys = (float)(h - 1) + offy;
        float xs = (float)(wt + px - 1) + offx;
        float y0f = floorf(ys);
        float x0f = floorf(xs);
        SampleParam p;
        p.y0 = (int)y0f;
        p.x0 = (int)x0f;
        p.ly = ys - y0f;
        p.lx = xs - x0f;
        sp[px] = p;
    }

    int lane = tid & 31;
    int wid = tid >> 5;
    int warp_m = (wid & 3) << 5;
    int warp_n = (wid >> 2) << 5;
    int r = lane & 3;
    int g = lane >> 2;

    float acc[2][4][4];
#pragma unroll
    for (int mi = 0; mi < 2; mi++)
#pragma unroll
        for (int ni = 0; ni < 4; ni++)
#pragma unroll
            for (int q = 0; q < 4; q++) acc[mi][ni][q] = 0.f;

    int half = lane >> 4;
    int cl = lane & 15;
    const float4* xtb4 = (const float4*)(g_xt + (size_t)b * HW * Cin) + cl;
    int px0 = wid << 4;

    for (int k = 0; k < 9; k++) {
        __syncthreads();

        {
            const uint4* src = (const uint4*)(g_wh + (size_t)k * OUTC * Cin);
            for (int i = tid; i < OUTC * Cin / 8; i += 256) {
                int o = i >> 3;
                int c8 = i & 7;
                *(uint4*)(wsm + o * SH32 + c8 * 4) = src[i];
            }
        }

#pragma unroll 4
        for (int s = 0; s < 8; s++) {
            int px = px0 + 2 * s + half;
            SampleParam p = sp[px];
            float hy = 1.f - p.ly, hx = 1.f - p.lx;
            float w00 = hy * hx, w01 = hy * p.lx;
            float w10 = p.ly * hx, w11 = p.ly * p.lx;
            bool y0k = ((unsigned)p.y0 < (unsigned)H);
            bool y1k = ((unsigned)(p.y0 + 1) < (unsigned)H);
            bool x0k = ((unsigned)p.x0 < (unsigned)W);
            bool x1k = ((unsigned)(p.x0 + 1) < (unsigned)W);
            const float4* base = xtb4 + (ptrdiff_t)(p.y0 * W + p.x0) * (Cin / 4);
            float4 z = make_float4(0.f, 0.f, 0.f, 0.f);
            float4 v00 = (y0k && x0k) ? base[0] : z;
            float4 v01 = (y0k && x1k) ? base[Cin / 4] : z;
            float4 v10 = (y1k && x0k) ? base[(ptrdiff_t)W * (Cin / 4)] : z;
            float4 v11 = (y1k && x1k) ? base[(ptrdiff_t)(W + 1) * (Cin / 4)] : z;
            float rx = w00 * v00.x + w01 * v01.x + w10 * v10.x + w11 * v11.x;
            float ry = w00 * v00.y + w01 * v01.y + w10 * v10.y + w11 * v11.y;
            float rz = w00 * v00.z + w01 * v01.z + w10 * v10.z + w11 * v11.z;
            float rw = w00 * v00.w + w01 * v01.w + w10 * v10.w + w11 * v11.w;
            uint2 pv;
            asm("cvt.rn.f16x2.f32 %0, %1, %2;" : "=r"(pv.x) : "f"(ry), "f"(rx));
            asm("cvt.rn.f16x2.f32 %0, %1, %2;" : "=r"(pv.y) : "f"(rw), "f"(rz));
            *(uint2*)&ssm[px * SH32 + 2 * cl] = pv;
        }
        __syncthreads();

        if (k < 8 && tid < MTILE) {
            int kn = k + 1;
            int px = tid;
            float offy = offb[(size_t)(2 * kn) * HW + px];
            float offx = offb[(size_t)(2 * kn + 1) * HW + px];
            float ys = (float)(h + (kn / 3) - 1) + offy;
            float xs = (float)(wt + px + (kn % 3) - 1) + offx;
            float y0f = floorf(ys);
            float x0f = floorf(xs);
            SampleParam p;
            p.y0 = (int)y0f;
            p.x0 = (int)x0f;
            p.ly = ys - y0f;
            p.lx = xs - x0f;
            sp[px] = p;
        }

#pragma unroll
        for (int kk = 0; kk < 4; kk++) {
            int kb = kk << 3;
            uint32_t a[2][4];
#pragma unroll
            for (int mi = 0; mi < 2; mi++) {
                const uint32_t* ar = ssm + (warp_m + 16 * mi + g) * SH32 + kb + r;
                a[mi][0] = ar[0];
                a[mi][1] = ar[8 * SH32];
                a[mi][2] = ar[4];
                a[mi][3] = ar[8 * SH32 + 4];
            }
            uint32_t bb[4][2];
#pragma unroll
            for (int ni = 0; ni < 4; ni++) {
                const uint32_t* br = wsm + (warp_n + ni * 8 + g) * SH32 + kb + r;
                bb[ni][0] = br[0];
                bb[ni][1] = br[4];
            }
#pragma unroll
            for (int mi = 0; mi < 2; mi++)
#pragma unroll
                for (int ni = 0; ni < 4; ni++)
                    mma_f16(acc[mi][ni], a[mi], bb[ni]);
        }
    }

#pragma unroll
    for (int ni = 0; ni < 4; ni++) {
        int o = warp_n + ni * 8 + 2 * r;
        float bo0 = b_def[o];
        float bo1 = b_def[o + 1];
        float* ob0 = out + ((size_t)(b * OUTC + o)) * HW + h * W + wt;
        float* ob1 = ob0 + HW;
#pragma unroll
        for (int mi = 0; mi < 2; mi++) {
            int px = warp_m + mi * 16 + g;
            ob0[px]     = acc[mi][ni][0] + bo0;
            ob1[px]     = acc[mi][ni][1] + bo1;
            ob0[px + 8] = acc[mi][ni][2] + bo0;
            ob1[px + 8] = acc[mi][ni][3] + bo1;
        }
    }
}

// ---------------------------------------------------------------------------
extern "C" void kernel_launch(void* const* d_in, const int* in_sizes, int n_in,
                              void* d_out, int out_size)
{
    const float* x     = (const float*)d_in[0];
    const float* w_off = (const float*)d_in[1];
    const float* b_off = (const float*)d_in[2];
    const float* w_def = (const float*)d_in[3];
    const float* b_def = (const float*)d_in[4];
    float* out = (float*)d_out;

    cudaFuncSetAttribute(deform_kernel,
                         cudaFuncAttributeMaxDynamicSharedMemorySize, DSMEM_BYTES);
    cudaFuncSetAttribute(offsets_kernel,
                         cudaFuncAttributeMaxDynamicSharedMemorySize, OFF_DSMEM);

    prep_wdef_kernel<<<(9 * OUTC * Cin + 255) / 256, 256>>>(w_def);
    prep_woff_kernel<<<(9 * OJ * Cin + 255) / 256, 256>>>(w_off);
    transpose_x_kernel<<<Bsz * H * (W / 32), 256>>>(x);
    offsets_kernel<<<Bsz * H * (W / MTILE), 256, OFF_DSMEM>>>(b_off);
    deform_kernel<<<Bsz * H * (W / MTILE), 256, DSMEM_BYTES>>>(b_def, out);
}

// round 10
// speedup vs baseline: 2.2595x; 1.1908x over previous
#include <cuda_runtime.h>
#include <cuda_fp16.h>
#include <cstdint>

#define Bsz 4
#define Cin 64
#define OUTC 64
#define H 256
#define W 256
#define HW (H*W)

#define MTILE 128          // pixels per CTA (half row)
#define SH 72              // ssm/wsm stride in halves (64 + 8 pad) -> conflict-free
#define SH32 (SH/2)        // = 36 u32 per row

#define OJ 24              // offset channels 18 padded to 24

// Scratch (device globals — no allocation allowed)
__device__ float g_offs[(size_t)Bsz * 18 * HW];        // offset conv output (fp32-accurate)
__device__ __half g_wh[9 * OUTC * Cin];                // w_def -> [k][o][c] fp16
__device__ __half g_xh[(size_t)Bsz * HW * Cin];        // x NHWC fp16 hi (33.5MB)
__device__ __half g_xl[(size_t)Bsz * HW * Cin];        // x NHWC fp16 lo (33.5MB)
__device__ __half g_wo_hi[9 * OJ * Cin];               // w_off split hi [k][j][c]
__device__ __half g_wo_lo[9 * OJ * Cin];               // w_off split lo [k][j][c]

// ---------------------------------------------------------------------------
// helpers
// ---------------------------------------------------------------------------
__device__ __forceinline__ void mma_f16(float* d, const uint32_t* a, const uint32_t* b) {
    asm volatile(
        "mma.sync.aligned.m16n8k16.row.col.f32.f16.f16.f32 "
        "{%0,%1,%2,%3}, {%4,%5,%6,%7}, {%8,%9}, {%0,%1,%2,%3};"
        : "+f"(d[0]), "+f"(d[1]), "+f"(d[2]), "+f"(d[3])
        : "r"(a[0]), "r"(a[1]), "r"(a[2]), "r"(a[3]),
          "r"(b[0]), "r"(b[1]));
}

__device__ __forceinline__ uint32_t pack_f16x2(float lo, float hi) {
    uint32_t r;
    asm("cvt.rn.f16x2.f32 %0, %1, %2;" : "=r"(r) : "f"(hi), "f"(lo));
    return r;
}

__device__ __forceinline__ uint32_t bil4(uint32_t a, uint32_t b, uint32_t c, uint32_t d,
                                         __half2 w00, __half2 w01, __half2 w10, __half2 w11) {
    __half2 r = __hmul2(*(__half2*)&a, w00);
    r = __hfma2(*(__half2*)&b, w01, r);
    r = __hfma2(*(__half2*)&c, w10, r);
    r = __hfma2(*(__half2*)&d, w11, r);
    return *(uint32_t*)&r;
}

// ---------------------------------------------------------------------------
// Kernel 0a: w_def [o][c][ki][kj] -> g_wh[k][o][c] (fp16)
// ---------------------------------------------------------------------------
__global__ void prep_wdef_kernel(const float* __restrict__ w_def) {
    int idx = blockIdx.x * 256 + threadIdx.x;
    if (idx >= 9 * OUTC * Cin) return;
    int k = idx / (OUTC * Cin);
    int rem = idx - k * (OUTC * Cin);
    int o = rem / Cin;
    int c = rem - o * Cin;
    g_wh[idx] = __float2half_rn(w_def[(o * Cin + c) * 9 + k]);
}

// ---------------------------------------------------------------------------
// Kernel 0b: w_off [j][c][ki][kj] -> g_wo_{hi,lo}[k][j][c] fp16 split
// ---------------------------------------------------------------------------
__global__ void prep_woff_kernel(const float* __restrict__ w_off) {
    int idx = blockIdx.x * 256 + threadIdx.x;      // 13824
    if (idx >= 9 * OJ * Cin) return;
    int k = idx / (OJ * Cin);
    int rem = idx - k * (OJ * Cin);
    int j = rem / Cin;
    int c = rem - j * Cin;
    float v = (j < 18) ? w_off[((size_t)j * Cin + c) * 9 + k] : 0.f;
    __half hi = __float2half_rn(v);
    float lo = v - __half2float(hi);
    g_wo_hi[idx] = hi;
    g_wo_lo[idx] = __float2half_rn(lo);
}

// ---------------------------------------------------------------------------
// Kernel 0c: transpose x NCHW -> NHWC fp16 split (g_xh + g_xl)
// ---------------------------------------------------------------------------
__global__ void __launch_bounds__(256) transpose_x_kernel(const float* __restrict__ x) {
    __shared__ float t[Cin][33];
    int tid = threadIdx.x;
    int bx = blockIdx.x;
    int wt = (bx & 7) << 5;
    int h = (bx >> 3) & (H - 1);
    int b = bx >> 11;

    const float* xb = x + (size_t)b * Cin * HW + h * W + wt;
#pragma unroll
    for (int it = 0; it < 8; it++) {
        int c = it * 8 + (tid >> 5);
        int w = tid & 31;
        t[c][w] = xb[(size_t)c * HW + w];
    }
    __syncthreads();
    size_t base = ((size_t)(b * H + h) * W + wt) * Cin;
    uint32_t* xh = (uint32_t*)(g_xh + base);
    uint32_t* xl = (uint32_t*)(g_xl + base);
#pragma unroll
    for (int it = 0; it < 4; it++) {
        int w = it * 8 + (tid >> 5);
        int c2 = tid & 31;
        float a0 = t[2 * c2][w];
        float a1 = t[2 * c2 + 1][w];
        __half h0 = __float2half_rn(a0);
        __half h1 = __float2half_rn(a1);
        __half2 hp = __halves2half2(h0, h1);
        float l0 = a0 - __half2float(h0);
        float l1 = a1 - __half2float(h1);
        xh[w * (Cin / 2) + c2] = *(uint32_t*)&hp;
        xl[w * (Cin / 2) + c2] = pack_f16x2(l0, l1);
    }
}

// ---------------------------------------------------------------------------
// Kernel 1: offsets conv via fp16 split-precision MMA (fp32-accurate).
// D = Ah*Bh + Ah*Bl + Al*Bh. A hi/lo prestored fp16 -> staging is pure copy.
// ---------------------------------------------------------------------------
#define OFF_SSMH_U32 (MTILE * SH32)                 // 4608
#define OFF_WSM_U32  (OJ * SH32)                    // 864
#define OFF_DSMEM ((2 * OFF_SSMH_U32 + 2 * OFF_WSM_U32) * 4)   // 43776 B

__global__ void __launch_bounds__(256, 4) offsets_kernel(
    const float* __restrict__ b_off)
{
    extern __shared__ uint32_t dsm[];
    uint32_t* ssm_h = dsm;                              // fp16 [px][c] hi
    uint32_t* ssm_l = ssm_h + OFF_SSMH_U32;             // fp16 [px][c] lo
    uint32_t* wsm_h = ssm_l + OFF_SSMH_U32;             // fp16 [j][c] hi
    uint32_t* wsm_l = wsm_h + OFF_WSM_U32;              // fp16 [j][c] lo

    int tid = threadIdx.x;
    int bx = blockIdx.x;
    int wt = (bx & 1) << 7;
    int h = (bx >> 1) & (H - 1);
    int b = bx >> 9;

    int lane = tid & 31;
    int wid = tid >> 5;
    int r = lane & 3;
    int g = lane >> 2;
    int quarter = lane >> 3;           // 4 samples per warp-iter
    int cl8 = lane & 7;                // channel octet
    int px0 = wid << 4;                // warp's 16-px m-tile

    float acc[3][4];
#pragma unroll
    for (int ni = 0; ni < 3; ni++)
#pragma unroll
        for (int q = 0; q < 4; q++) acc[ni][q] = 0.f;

    const uint4* xh4 = (const uint4*)(g_xh + (size_t)b * HW * Cin) + cl8;
    const uint4* xl4 = (const uint4*)(g_xl + (size_t)b * HW * Cin) + cl8;

    for (int k = 0; k < 9; k++) {
        int dy = k / 3 - 1;
        int dx = k % 3 - 1;
        int y = h + dy;
        bool yok = ((unsigned)y < (unsigned)H);

        __syncthreads();   // ssm/wsm free of previous tap's readers

        // stage B hi+lo: 2 x 192 uint4
        {
            const uint4* sh = (const uint4*)(g_wo_hi + (size_t)k * OJ * Cin);
            const uint4* sl = (const uint4*)(g_wo_lo + (size_t)k * OJ * Cin);
            for (int i = tid; i < 2 * OJ * Cin / 8; i += 256) {
                int hf = (i >= OJ * Cin / 8);
                int ii = i - hf * (OJ * Cin / 8);
                int j = ii >> 3;
                int c8 = ii & 7;
                uint4 v = hf ? sl[ii] : sh[ii];
                *(uint4*)((hf ? wsm_l : wsm_h) + j * SH32 + c8 * 4) = v;
            }
        }

        // stage A hi+lo: 4 iters, 4 samples/warp, lane = 8 channels (pure copy)
        uint4 z4 = make_uint4(0, 0, 0, 0);
#pragma unroll
        for (int s = 0; s < 4; s++) {
            int px = px0 + 4 * s + quarter;
            int xw = wt + px + dx;
            bool ok = yok && ((unsigned)xw < (unsigned)W);
            ptrdiff_t pix = (ptrdiff_t)y * W + xw;
            uint4 vh = ok ? xh4[pix * (Cin / 8)] : z4;
            uint4 vl = ok ? xl4[pix * (Cin / 8)] : z4;
            *(uint4*)&ssm_h[px * SH32 + cl8 * 4] = vh;
            *(uint4*)&ssm_l[px * SH32 + cl8 * 4] = vl;
        }
        __syncthreads();

        // MMA: 4 k-steps x 3 n-tiles x (Ah*Bh + Ah*Bl + Al*Bh)
#pragma unroll
        for (int kk = 0; kk < 4; kk++) {
            int kb = kk << 3;
            uint32_t ah[4], al[4];
            const uint32_t* arh = ssm_h + (px0 + g) * SH32 + kb + r;
            const uint32_t* arl = ssm_l + (px0 + g) * SH32 + kb + r;
            ah[0] = arh[0];
            ah[1] = arh[8 * SH32];
            ah[2] = arh[4];
            ah[3] = arh[8 * SH32 + 4];
            al[0] = arl[0];
            al[1] = arl[8 * SH32];
            al[2] = arl[4];
            al[3] = arl[8 * SH32 + 4];
#pragma unroll
            for (int ni = 0; ni < 3; ni++) {
                const uint32_t* brh = wsm_h + (ni * 8 + g) * SH32 + kb + r;
                const uint32_t* brl = wsm_l + (ni * 8 + g) * SH32 + kb + r;
                uint32_t bh[2] = { brh[0], brh[4] };
                uint32_t bl[2] = { brl[0], brl[4] };
                mma_f16(acc[ni], ah, bh);
                mma_f16(acc[ni], ah, bl);
                mma_f16(acc[ni], al, bh);
            }
        }
    }

    // epilogue: j = ni*8 + 2r (+1); rows px0+g, px0+g+8; guard j < 18
#pragma unroll
    for (int ni = 0; ni < 3; ni++) {
        int j = ni * 8 + 2 * r;
        if (j < 18) {
            float* ob = g_offs + ((size_t)b * 18 + j) * HW + h * W + wt;
            float bj = b_off[j];
            ob[px0 + g]     = acc[ni][0] + bj;
            ob[px0 + g + 8] = acc[ni][2] + bj;
        }
        if (j + 1 < 18) {
            float* ob = g_offs + ((size_t)b * 18 + j + 1) * HW + h * W + wt;
            float bj = b_off[j + 1];
            ob[px0 + g]     = acc[ni][1] + bj;
            ob[px0 + g + 8] = acc[ni][3] + bj;
        }
    }
}

// ---------------------------------------------------------------------------
// Kernel 2: deform — fp16 NHWC gather (hi only), half2 bilinear, fp16 MMA
// ---------------------------------------------------------------------------
struct __align__(16) SampleParam { int y0; int x0; float ly; float lx; };

#define SSM_U32 (MTILE * SH32)            // 4608 u32 = 18432 B
#define WSM_U32 (OUTC * SH32)             // 2304 u32 =  9216 B
#define DSMEM_BYTES ((SSM_U32 + WSM_U32) * 4 + MTILE * 16)   // 29696 B

__global__ void __launch_bounds__(256, 4) deform_kernel(
    const float* __restrict__ b_def,
    float* __restrict__ out)
{
    extern __shared__ uint32_t dsm[];
    uint32_t* ssm = dsm;                        // fp16 [px][c], u32 view
    uint32_t* wsm = dsm + SSM_U32;              // fp16 [o][c], u32 view
    SampleParam* sp = (SampleParam*)(dsm + SSM_U32 + WSM_U32);   // [px], one tap

    int tid = threadIdx.x;
    int bx = blockIdx.x;
    int wt = (bx & 1) << 7;
    int h = (bx >> 1) & (H - 1);
    int b = bx >> 9;

    const float* offb = g_offs + (size_t)b * 18 * HW + h * W + wt;

    if (tid < MTILE) {
        int px = tid;
        float offy = offb[0 * HW + px];
        float offx = offb[1 * HW + px];
        float ys = (float)(h - 1) + offy;
        float xs = (float)(wt + px - 1) + offx;
        float y0f = floorf(ys);
        float x0f = floorf(xs);
        SampleParam p;
        p.y0 = (int)y0f;
        p.x0 = (int)x0f;
        p.ly = ys - y0f;
        p.lx = xs - x0f;
        sp[px] = p;
    }

    int lane = tid & 31;
    int wid = tid >> 5;
    int warp_m = (wid & 3) << 5;
    int warp_n = (wid >> 2) << 5;
    int r = lane & 3;
    int g = lane >> 2;

    float acc[2][4][4];
#pragma unroll
    for (int mi = 0; mi < 2; mi++)
#pragma unroll
        for (int ni = 0; ni < 4; ni++)
#pragma unroll
            for (int q = 0; q < 4; q++) acc[mi][ni][q] = 0.f;

    int quarter = lane >> 3;           // 4 samples per warp-iter
    int cl8 = lane & 7;                // channel octet
    const uint4* xh4 = (const uint4*)(g_xh + (size_t)b * HW * Cin) + cl8;
    int px0 = wid << 4;

    for (int k = 0; k < 9; k++) {
        __syncthreads();

        // stage fp16 weights [o][c]
        {
            const uint4* src = (const uint4*)(g_wh + (size_t)k * OUTC * Cin);
            for (int i = tid; i < OUTC * Cin / 8; i += 256) {
                int o = i >> 3;
                int c8 = i & 7;
                *(uint4*)(wsm + o * SH32 + c8 * 4) = src[i];
            }
        }

        // gather: 4 iters, 4 samples/warp, lane = 8 channels fp16 (LDG.128)
        uint4 z4 = make_uint4(0, 0, 0, 0);
#pragma unroll
        for (int s = 0; s < 4; s++) {
            int px = px0 + 4 * s + quarter;
            SampleParam p = sp[px];
            float hy = 1.f - p.ly, hx = 1.f - p.lx;
            __half2 w00h = __float2half2_rn(hy * hx);
            __half2 w01h = __float2half2_rn(hy * p.lx);
            __half2 w10h = __float2half2_rn(p.ly * hx);
            __half2 w11h = __float2half2_rn(p.ly * p.lx);
            bool y0k = ((unsigned)p.y0 < (unsigned)H);
            bool y1k = ((unsigned)(p.y0 + 1) < (unsigned)H);
            bool x0k = ((unsigned)p.x0 < (unsigned)W);
            bool x1k = ((unsigned)(p.x0 + 1) < (unsigned)W);
            const uint4* base = xh4 + ((ptrdiff_t)p.y0 * W + p.x0) * (Cin / 8);
            uint4 v00 = (y0k && x0k) ? base[0] : z4;
            uint4 v01 = (y0k && x1k) ? base[Cin / 8] : z4;
            uint4 v10 = (y1k && x0k) ? base[(ptrdiff_t)W * (Cin / 8)] : z4;
            uint4 v11 = (y1k && x1k) ? base[(ptrdiff_t)(W + 1) * (Cin / 8)] : z4;
            uint4 res;
            res.x = bil4(v00.x, v01.x, v10.x, v11.x, w00h, w01h, w10h, w11h);
            res.y = bil4(v00.y, v01.y, v10.y, v11.y, w00h, w01h, w10h, w11h);
            res.z = bil4(v00.z, v01.z, v10.z, v11.z, w00h, w01h, w10h, w11h);
            res.w = bil4(v00.w, v01.w, v10.w, v11.w, w00h, w01h, w10h, w11h);
            *(uint4*)&ssm[px * SH32 + cl8 * 4] = res;
        }
        __syncthreads();

        // prefetch next tap's sampling params (overlaps MMA)
        if (k < 8 && tid < MTILE) {
            int kn = k + 1;
            int px = tid;
            float offy = offb[(size_t)(2 * kn) * HW + px];
            float offx = offb[(size_t)(2 * kn + 1) * HW + px];
            float ys = (float)(h + (kn / 3) - 1) + offy;
            float xs = (float)(wt + px + (kn % 3) - 1) + offx;
            float y0f = floorf(ys);
            float x0f = floorf(xs);
            SampleParam p;
            p.y0 = (int)y0f;
            p.x0 = (int)x0f;
            p.ly = ys - y0f;
            p.lx = xs - x0f;
            sp[px] = p;
        }

        // MMA: 4 k-steps of m16n8k16
#pragma unroll
        for (int kk = 0; kk < 4; kk++) {
            int kb = kk << 3;
            uint32_t a[2][4];
#pragma unroll
            for (int mi = 0; mi < 2; mi++) {
                const uint32_t* ar = ssm + (warp_m + 16 * mi + g) * SH32 + kb + r;
                a[mi][0] = ar[0];
                a[mi][1] = ar[8 * SH32];
                a[mi][2] = ar[4];
                a[mi][3] = ar[8 * SH32 + 4];
            }
            uint32_t bb[4][2];
#pragma unroll
            for (int ni = 0; ni < 4; ni++) {
                const uint32_t* br = wsm + (warp_n + ni * 8 + g) * SH32 + kb + r;
                bb[ni][0] = br[0];
                bb[ni][1] = br[4];
            }
#pragma unroll
            for (int mi = 0; mi < 2; mi++)
#pragma unroll
                for (int ni = 0; ni < 4; ni++)
                    mma_f16(acc[mi][ni], a[mi], bb[ni]);
        }
    }

    // ---- epilogue: bias + direct stores (NCHW out) ----
#pragma unroll
    for (int ni = 0; ni < 4; ni++) {
        int o = warp_n + ni * 8 + 2 * r;
        float bo0 = b_def[o];
        float bo1 = b_def[o + 1];
        float* ob0 = out + ((size_t)(b * OUTC + o)) * HW + h * W + wt;
        float* ob1 = ob0 + HW;
#pragma unroll
        for (int mi = 0; mi < 2; mi++) {
            int px = warp_m + mi * 16 + g;
            ob0[px]     = acc[mi][ni][0] + bo0;
            ob1[px]     = acc[mi][ni][1] + bo1;
            ob0[px + 8] = acc[mi][ni][2] + bo0;
            ob1[px + 8] = acc[mi][ni][3] + bo1;
        }
    }
}

// ---------------------------------------------------------------------------
extern "C" void kernel_launch(void* const* d_in, const int* in_sizes, int n_in,
                              void* d_out, int out_size)
{
    const float* x     = (const float*)d_in[0];
    const float* w_off = (const float*)d_in[1];
    const float* b_off = (const float*)d_in[2];
    const float* w_def = (const float*)d_in[3];
    const float* b_def = (const float*)d_in[4];
    float* out = (float*)d_out;

    cudaFuncSetAttribute(deform_kernel,
                         cudaFuncAttributeMaxDynamicSharedMemorySize, DSMEM_BYTES);
    cudaFuncSetAttribute(offsets_kernel,
                         cudaFuncAttributeMaxDynamicSharedMemorySize, OFF_DSMEM);

    prep_wdef_kernel<<<(9 * OUTC * Cin + 255) / 256, 256>>>(w_def);
    prep_woff_kernel<<<(9 * OJ * Cin + 255) / 256, 256>>>(w_off);
    transpose_x_kernel<<<Bsz * H * (W / 32), 256>>>(x);
    offsets_kernel<<<Bsz * H * (W / MTILE), 256, OFF_DSMEM>>>(b_off);
    deform_kernel<<<Bsz * H * (W / MTILE), 256, DSMEM_BYTES>>>(b_def, out);
}

// round 11
// speedup vs baseline: 2.4060x; 1.0648x over previous
#include <cuda_runtime.h>
#include <cuda_fp16.h>
#include <cstdint>

#define Bsz 4
#define Cin 64
#define OUTC 64
#define H 256
#define W 256
#define HW (H*W)

#define MTILE 128          // pixels per CTA (half row)
#define SH 72              // ssm/wsm stride in halves (64 + 8 pad) -> conflict-free
#define SH32 (SH/2)        // = 36 u32 per row

#define OJ 24              // offset channels 18 padded to 24
#define HPX 130            // offsets A-halo pixels: -1 .. 128

// Scratch (device globals — no allocation allowed)
__device__ float g_offs[(size_t)Bsz * 18 * HW];        // offset conv output (fp32-accurate)
__device__ __half g_wh[9 * OUTC * Cin];                // w_def -> [k][o][c] fp16
__device__ __half g_xh[(size_t)Bsz * HW * Cin];        // x NHWC fp16 hi (33.5MB)
__device__ __half g_xl[(size_t)Bsz * HW * Cin];        // x NHWC fp16 lo (33.5MB)
__device__ __half g_wo_hi[9 * OJ * Cin];               // w_off split hi [k][j][c]
__device__ __half g_wo_lo[9 * OJ * Cin];               // w_off split lo [k][j][c]

// ---------------------------------------------------------------------------
// helpers
// ---------------------------------------------------------------------------
__device__ __forceinline__ void mma_f16(float* d, const uint32_t* a, const uint32_t* b) {
    asm volatile(
        "mma.sync.aligned.m16n8k16.row.col.f32.f16.f16.f32 "
        "{%0,%1,%2,%3}, {%4,%5,%6,%7}, {%8,%9}, {%0,%1,%2,%3};"
        : "+f"(d[0]), "+f"(d[1]), "+f"(d[2]), "+f"(d[3])
        : "r"(a[0]), "r"(a[1]), "r"(a[2]), "r"(a[3]),
          "r"(b[0]), "r"(b[1]));
}

__device__ __forceinline__ uint32_t pack_f16x2(float lo, float hi) {
    uint32_t r;
    asm("cvt.rn.f16x2.f32 %0, %1, %2;" : "=r"(r) : "f"(hi), "f"(lo));
    return r;
}

__device__ __forceinline__ uint32_t bil4(uint32_t a, uint32_t b, uint32_t c, uint32_t d,
                                         __half2 w00, __half2 w01, __half2 w10, __half2 w11) {
    __half2 r = __hmul2(*(__half2*)&a, w00);
    r = __hfma2(*(__half2*)&b, w01, r);
    r = __hfma2(*(__half2*)&c, w10, r);
    r = __hfma2(*(__half2*)&d, w11, r);
    return *(uint32_t*)&r;
}

// ---------------------------------------------------------------------------
// Kernel 0a: w_def [o][c][ki][kj] -> g_wh[k][o][c] (fp16)
// ---------------------------------------------------------------------------
__global__ void prep_wdef_kernel(const float* __restrict__ w_def) {
    int idx = blockIdx.x * 256 + threadIdx.x;
    if (idx >= 9 * OUTC * Cin) return;
    int k = idx / (OUTC * Cin);
    int rem = idx - k * (OUTC * Cin);
    int o = rem / Cin;
    int c = rem - o * Cin;
    g_wh[idx] = __float2half_rn(w_def[(o * Cin + c) * 9 + k]);
}

// ---------------------------------------------------------------------------
// Kernel 0b: w_off [j][c][ki][kj] -> g_wo_{hi,lo}[k][j][c] fp16 split
// ---------------------------------------------------------------------------
__global__ void prep_woff_kernel(const float* __restrict__ w_off) {
    int idx = blockIdx.x * 256 + threadIdx.x;      // 13824
    if (idx >= 9 * OJ * Cin) return;
    int k = idx / (OJ * Cin);
    int rem = idx - k * (OJ * Cin);
    int j = rem / Cin;
    int c = rem - j * Cin;
    float v = (j < 18) ? w_off[((size_t)j * Cin + c) * 9 + k] : 0.f;
    __half hi = __float2half_rn(v);
    float lo = v - __half2float(hi);
    g_wo_hi[idx] = hi;
    g_wo_lo[idx] = __float2half_rn(lo);
}

// ---------------------------------------------------------------------------
// Kernel 0c: transpose x NCHW -> NHWC fp16 split (g_xh + g_xl)
// ---------------------------------------------------------------------------
__global__ void __launch_bounds__(256) transpose_x_kernel(const float* __restrict__ x) {
    __shared__ float t[Cin][33];
    int tid = threadIdx.x;
    int bx = blockIdx.x;
    int wt = (bx & 7) << 5;
    int h = (bx >> 3) & (H - 1);
    int b = bx >> 11;

    const float* xb = x + (size_t)b * Cin * HW + h * W + wt;
#pragma unroll
    for (int it = 0; it < 8; it++) {
        int c = it * 8 + (tid >> 5);
        int w = tid & 31;
        t[c][w] = xb[(size_t)c * HW + w];
    }
    __syncthreads();
    size_t base = ((size_t)(b * H + h) * W + wt) * Cin;
    uint32_t* xh = (uint32_t*)(g_xh + base);
    uint32_t* xl = (uint32_t*)(g_xl + base);
#pragma unroll
    for (int it = 0; it < 4; it++) {
        int w = it * 8 + (tid >> 5);
        int c2 = tid & 31;
        float a0 = t[2 * c2][w];
        float a1 = t[2 * c2 + 1][w];
        __half h0 = __float2half_rn(a0);
        __half h1 = __float2half_rn(a1);
        __half2 hp = __halves2half2(h0, h1);
        float l0 = a0 - __half2float(h0);
        float l1 = a1 - __half2float(h1);
        xh[w * (Cin / 2) + c2] = *(uint32_t*)&hp;
        xl[w * (Cin / 2) + c2] = pack_f16x2(l0, l1);
    }
}

// ---------------------------------------------------------------------------
// Kernel 1: offsets conv, fp16 split MMA, ROW-REUSE:
// stage each image row once (130-px halo, hi+lo); the 3 dx-taps of that row
// read A-frags at shifted smem rows. B ping-pong staged under previous MMA.
// Arithmetic identical to R10 (same tap order, same MMA accumulation).
// ---------------------------------------------------------------------------
#define OFF_SSM_U32 (HPX * SH32)                    // 4680 per half
#define OFF_WTAP_U32 (2 * OJ * SH32)                // 1728 per tap (hi+lo)
#define OFF_DSMEM ((2 * OFF_SSM_U32 + 2 * OFF_WTAP_U32) * 4)   // 51264 B

__global__ void __launch_bounds__(256, 4) offsets_kernel(
    const float* __restrict__ b_off)
{
    extern __shared__ uint32_t dsm[];
    uint32_t* ssm_h = dsm;                              // [130 px][c] hi
    uint32_t* ssm_l = ssm_h + OFF_SSM_U32;              // lo
    uint32_t* wbuf = ssm_l + OFF_SSM_U32;               // 2 x (hi 864 | lo 864)

    int tid = threadIdx.x;
    int bx = blockIdx.x;
    int wt = (bx & 1) << 7;
    int h = (bx >> 1) & (H - 1);
    int b = bx >> 9;

    int lane = tid & 31;
    int wid = tid >> 5;
    int r = lane & 3;
    int g = lane >> 2;
    int px0 = wid << 4;                // warp's 16-px m-tile

    float acc[3][4];
#pragma unroll
    for (int ni = 0; ni < 3; ni++)
#pragma unroll
        for (int q = 0; q < 4; q++) acc[ni][q] = 0.f;

    const uint4* xh4 = (const uint4*)(g_xh + (size_t)b * HW * Cin);
    const uint4* xl4 = (const uint4*)(g_xl + (size_t)b * HW * Cin);

    // ---- helpers as lambdas ----
    auto stageB = [&](int k, int buf) {
        uint32_t* wh = wbuf + buf * OFF_WTAP_U32;
        uint32_t* wl = wh + OJ * SH32;
        const uint4* sh = (const uint4*)(g_wo_hi + (size_t)k * OJ * Cin);
        const uint4* sl = (const uint4*)(g_wo_lo + (size_t)k * OJ * Cin);
        for (int i = tid; i < 2 * OJ * Cin / 8; i += 256) {
            int hf = (i >= OJ * Cin / 8);
            int ii = i - hf * (OJ * Cin / 8);
            int j = ii >> 3;
            int c8 = ii & 7;
            uint4 v = hf ? sl[ii] : sh[ii];
            *(uint4*)((hf ? wl : wh) + j * SH32 + c8 * 4) = v;
        }
    };

    auto mmaTap = [&](int t, int buf) {   // t = dx+1: A row = px + t
        uint32_t* wh = wbuf + buf * OFF_WTAP_U32;
        uint32_t* wl = wh + OJ * SH32;
#pragma unroll
        for (int kk = 0; kk < 4; kk++) {
            int kb = kk << 3;
            uint32_t ah[4], al[4];
            const uint32_t* arh = ssm_h + (px0 + g + t) * SH32 + kb + r;
            const uint32_t* arl = ssm_l + (px0 + g + t) * SH32 + kb + r;
            ah[0] = arh[0];
            ah[1] = arh[8 * SH32];
            ah[2] = arh[4];
            ah[3] = arh[8 * SH32 + 4];
            al[0] = arl[0];
            al[1] = arl[8 * SH32];
            al[2] = arl[4];
            al[3] = arl[8 * SH32 + 4];
#pragma unroll
            for (int ni = 0; ni < 3; ni++) {
                const uint32_t* brh = wh + (ni * 8 + g) * SH32 + kb + r;
                const uint32_t* brl = wl + (ni * 8 + g) * SH32 + kb + r;
                uint32_t bh[2] = { brh[0], brh[4] };
                uint32_t bl[2] = { brl[0], brl[4] };
                mma_f16(acc[ni], ah, bh);
                mma_f16(acc[ni], ah, bl);
                mma_f16(acc[ni], al, bh);
            }
        }
    };

    for (int rr = 0; rr < 3; rr++) {
        int y = h + rr - 1;
        bool yok = ((unsigned)y < (unsigned)H);

        __syncthreads();   // prev row's ssm readers + buf0 readers done

        // stage A row (130-px halo, hi+lo): 2*1040 uint4 over 256 threads
        {
            uint4 z4 = make_uint4(0, 0, 0, 0);
            for (int i = tid; i < 2 * HPX * 8; i += 256) {
                int hf = (i >= HPX * 8);
                int ii = i - hf * (HPX * 8);
                int pxs = ii >> 3;         // 0..129  (image w = wt + pxs - 1)
                int c8 = ii & 7;
                int xw = wt + pxs - 1;
                bool ok = yok && ((unsigned)xw < (unsigned)W);
                ptrdiff_t pix = (ptrdiff_t)y * W + xw;
                uint4 v = ok ? (hf ? xl4[pix * (Cin / 8) + c8]
                                   : xh4[pix * (Cin / 8) + c8]) : z4;
                *(uint4*)((hf ? ssm_l : ssm_h) + pxs * SH32 + c8 * 4) = v;
            }
        }
        stageB(3 * rr, 0);
        __syncthreads();

        stageB(3 * rr + 1, 1);
        mmaTap(0, 0);
        __syncthreads();

        stageB(3 * rr + 2, 0);
        mmaTap(1, 1);
        __syncthreads();

        mmaTap(2, 0);
    }

    // epilogue: j = ni*8 + 2r (+1); rows px0+g, px0+g+8; guard j < 18
#pragma unroll
    for (int ni = 0; ni < 3; ni++) {
        int j = ni * 8 + 2 * r;
        if (j < 18) {
            float* ob = g_offs + ((size_t)b * 18 + j) * HW + h * W + wt;
            float bj = b_off[j];
            ob[px0 + g]     = acc[ni][0] + bj;
            ob[px0 + g + 8] = acc[ni][2] + bj;
        }
        if (j + 1 < 18) {
            float* ob = g_offs + ((size_t)b * 18 + j + 1) * HW + h * W + wt;
            float bj = b_off[j + 1];
            ob[px0 + g]     = acc[ni][1] + bj;
            ob[px0 + g + 8] = acc[ni][3] + bj;
        }
    }
}

// ---------------------------------------------------------------------------
// Kernel 2: deform — fp16 NHWC gather (hi only), half2 bilinear, fp16 MMA
// (unchanged from R10 — protected win)
// ---------------------------------------------------------------------------
struct __align__(16) SampleParam { int y0; int x0; float ly; float lx; };

#define SSM_U32 (MTILE * SH32)            // 4608 u32 = 18432 B
#define WSM_U32 (OUTC * SH32)             // 2304 u32 =  9216 B
#define DSMEM_BYTES ((SSM_U32 + WSM_U32) * 4 + MTILE * 16)   // 29696 B

__global__ void __launch_bounds__(256, 4) deform_kernel(
    const float* __restrict__ b_def,
    float* __restrict__ out)
{
    extern __shared__ uint32_t dsm[];
    uint32_t* ssm = dsm;                        // fp16 [px][c], u32 view
    uint32_t* wsm = dsm + SSM_U32;              // fp16 [o][c], u32 view
    SampleParam* sp = (SampleParam*)(dsm + SSM_U32 + WSM_U32);   // [px], one tap

    int tid = threadIdx.x;
    int bx = blockIdx.x;
    int wt = (bx & 1) << 7;
    int h = (bx >> 1) & (H - 1);
    int b = bx >> 9;

    const float* offb = g_offs + (size_t)b * 18 * HW + h * W + wt;

    if (tid < MTILE) {
        int px = tid;
        float offy = offb[0 * HW + px];
        float offx = offb[1 * HW + px];
        float ys = (float)(h - 1) + offy;
        float xs = (float)(wt + px - 1) + offx;
        float y0f = floorf(ys);
        float x0f = floorf(xs);
        SampleParam p;
        p.y0 = (int)y0f;
        p.x0 = (int)x0f;
        p.ly = ys - y0f;
        p.lx = xs - x0f;
        sp[px] = p;
    }

    int lane = tid & 31;
    int wid = tid >> 5;
    int warp_m = (wid & 3) << 5;
    int warp_n = (wid >> 2) << 5;
    int r = lane & 3;
    int g = lane >> 2;

    float acc[2][4][4];
#pragma unroll
    for (int mi = 0; mi < 2; mi++)
#pragma unroll
        for (int ni = 0; ni < 4; ni++)
#pragma unroll
            for (int q = 0; q < 4; q++) acc[mi][ni][q] = 0.f;

    int quarter = lane >> 3;           // 4 samples per warp-iter
    int cl8 = lane & 7;                // channel octet
    const uint4* xh4 = (const uint4*)(g_xh + (size_t)b * HW * Cin) + cl8;
    int px0 = wid << 4;

    for (int k = 0; k < 9; k++) {
        __syncthreads();

        // stage fp16 weights [o][c]
        {
            const uint4* src = (const uint4*)(g_wh + (size_t)k * OUTC * Cin);
            for (int i = tid; i < OUTC * Cin / 8; i += 256) {
                int o = i >> 3;
                int c8 = i & 7;
                *(uint4*)(wsm + o * SH32 + c8 * 4) = src[i];
            }
        }

        // gather: 4 iters, 4 samples/warp, lane = 8 channels fp16 (LDG.128)
        uint4 z4 = make_uint4(0, 0, 0, 0);
#pragma unroll
        for (int s = 0; s < 4; s++) {
            int px = px0 + 4 * s + quarter;
            SampleParam p = sp[px];
            float hy = 1.f - p.ly, hx = 1.f - p.lx;
            __half2 w00h = __float2half2_rn(hy * hx);
            __half2 w01h = __float2half2_rn(hy * p.lx);
            __half2 w10h = __float2half2_rn(p.ly * hx);
            __half2 w11h = __float2half2_rn(p.ly * p.lx);
            bool y0k = ((unsigned)p.y0 < (unsigned)H);
            bool y1k = ((unsigned)(p.y0 + 1) < (unsigned)H);
            bool x0k = ((unsigned)p.x0 < (unsigned)W);
            bool x1k = ((unsigned)(p.x0 + 1) < (unsigned)W);
            const uint4* base = xh4 + ((ptrdiff_t)p.y0 * W + p.x0) * (Cin / 8);
            uint4 v00 = (y0k && x0k) ? base[0] : z4;
            uint4 v01 = (y0k && x1k) ? base[Cin / 8] : z4;
            uint4 v10 = (y1k && x0k) ? base[(ptrdiff_t)W * (Cin / 8)] : z4;
            uint4 v11 = (y1k && x1k) ? base[(ptrdiff_t)(W + 1) * (Cin / 8)] : z4;
            uint4 res;
            res.x = bil4(v00.x, v01.x, v10.x, v11.x, w00h, w01h, w10h, w11h);
            res.y = bil4(v00.y, v01.y, v10.y, v11.y, w00h, w01h, w10h, w11h);
            res.z = bil4(v00.z, v01.z, v10.z, v11.z, w00h, w01h, w10h, w11h);
            res.w = bil4(v00.w, v01.w, v10.w, v11.w, w00h, w01h, w10h, w11h);
            *(uint4*)&ssm[px * SH32 + cl8 * 4] = res;
        }
        __syncthreads();

        // prefetch next tap's sampling params (overlaps MMA)
        if (k < 8 && tid < MTILE) {
            int kn = k + 1;
            int px = tid;
            float offy = offb[(size_t)(2 * kn) * HW + px];
            float offx = offb[(size_t)(2 * kn + 1) * HW + px];
            float ys = (float)(h + (kn / 3) - 1) + offy;
            float xs = (float)(wt + px + (kn % 3) - 1) + offx;
            float y0f = floorf(ys);
            float x0f = floorf(xs);
            SampleParam p;
            p.y0 = (int)y0f;
            p.x0 = (int)x0f;
            p.ly = ys - y0f;
            p.lx = xs - x0f;
            sp[px] = p;
        }

        // MMA: 4 k-steps of m16n8k16
#pragma unroll
        for (int kk = 0; kk < 4; kk++) {
            int kb = kk << 3;
            uint32_t a[2][4];
#pragma unroll
            for (int mi = 0; mi < 2; mi++) {
                const uint32_t* ar = ssm + (warp_m + 16 * mi + g) * SH32 + kb + r;
                a[mi][0] = ar[0];
                a[mi][1] = ar[8 * SH32];
                a[mi][2] = ar[4];
                a[mi][3] = ar[8 * SH32 + 4];
            }
            uint32_t bb[4][2];
#pragma unroll
            for (int ni = 0; ni < 4; ni++) {
                const uint32_t* br = wsm + (warp_n + ni * 8 + g) * SH32 + kb + r;
                bb[ni][0] = br[0];
                bb[ni][1] = br[4];
            }
#pragma unroll
            for (int mi = 0; mi < 2; mi++)
#pragma unroll
                for (int ni = 0; ni < 4; ni++)
                    mma_f16(acc[mi][ni], a[mi], bb[ni]);
        }
    }

    // ---- epilogue: bias + direct stores (NCHW out) ----
#pragma unroll
    for (int ni = 0; ni < 4; ni++) {
        int o = warp_n + ni * 8 + 2 * r;
        float bo0 = b_def[o];
        float bo1 = b_def[o + 1];
        float* ob0 = out + ((size_t)(b * OUTC + o)) * HW + h * W + wt;
        float* ob1 = ob0 + HW;
#pragma unroll
        for (int mi = 0; mi < 2; mi++) {
            int px = warp_m + mi * 16 + g;
            ob0[px]     = acc[mi][ni][0] + bo0;
            ob1[px]     = acc[mi][ni][1] + bo1;
            ob0[px + 8] = acc[mi][ni][2] + bo0;
            ob1[px + 8] = acc[mi][ni][3] + bo1;
        }
    }
}

// ---------------------------------------------------------------------------
extern "C" void kernel_launch(void* const* d_in, const int* in_sizes, int n_in,
                              void* d_out, int out_size)
{
    const float* x     = (const float*)d_in[0];
    const float* w_off = (const float*)d_in[1];
    const float* b_off = (const float*)d_in[2];
    const float* w_def = (const float*)d_in[3];
    const float* b_def = (const float*)d_in[4];
    float* out = (float*)d_out;

    cudaFuncSetAttribute(deform_kernel,
                         cudaFuncAttributeMaxDynamicSharedMemorySize, DSMEM_BYTES);
    cudaFuncSetAttribute(offsets_kernel,
                         cudaFuncAttributeMaxDynamicSharedMemorySize, OFF_DSMEM);

    prep_wdef_kernel<<<(9 * OUTC * Cin + 255) / 256, 256>>>(w_def);
    prep_woff_kernel<<<(9 * OJ * Cin + 255) / 256, 256>>>(w_off);
    transpose_x_kernel<<<Bsz * H * (W / 32), 256>>>(x);
    offsets_kernel<<<Bsz * H * (W / MTILE), 256, OFF_DSMEM>>>(b_off);
    deform_kernel<<<Bsz * H * (W / MTILE), 256, DSMEM_BYTES>>>(b_def, out);
}

// round 12
// speedup vs baseline: 2.4387x; 1.0136x over previous
#include <cuda_runtime.h>
#include <cuda_fp16.h>
#include <cstdint>

#define Bsz 4
#define Cin 64
#define OUTC 64
#define H 256
#define W 256
#define HW (H*W)

#define MTILE 128          // pixels per CTA (half row)
#define SH 72              // ssm/wsm stride in halves (64 + 8 pad) -> conflict-free
#define SH32 (SH/2)        // = 36 u32 per row

#define OJ 24              // offset channels 18 padded to 24
#define HPX 130            // offsets A-halo pixels: -1 .. 128

// Scratch (device globals — no allocation allowed)
__device__ float g_offs[(size_t)Bsz * 18 * HW];        // offset conv output (fp32-accurate)
__device__ __half g_wh[9 * OUTC * Cin];                // w_def -> [k][o][c] fp16
__device__ __half g_xh[(size_t)Bsz * HW * Cin];        // x NHWC fp16 hi (33.5MB)
__device__ __half g_xl[(size_t)Bsz * HW * Cin];        // x NHWC fp16 lo (33.5MB)
__device__ __half g_wo_hi[9 * OJ * Cin];               // w_off split hi [k][j][c]
__device__ __half g_wo_lo[9 * OJ * Cin];               // w_off split lo [k][j][c]

// ---------------------------------------------------------------------------
// helpers
// ---------------------------------------------------------------------------
__device__ __forceinline__ void mma_f16(float* d, const uint32_t* a, const uint32_t* b) {
    asm volatile(
        "mma.sync.aligned.m16n8k16.row.col.f32.f16.f16.f32 "
        "{%0,%1,%2,%3}, {%4,%5,%6,%7}, {%8,%9}, {%0,%1,%2,%3};"
        : "+f"(d[0]), "+f"(d[1]), "+f"(d[2]), "+f"(d[3])
        : "r"(a[0]), "r"(a[1]), "r"(a[2]), "r"(a[3]),
          "r"(b[0]), "r"(b[1]));
}

__device__ __forceinline__ uint32_t pack_f16x2(float lo, float hi) {
    uint32_t r;
    asm("cvt.rn.f16x2.f32 %0, %1, %2;" : "=r"(r) : "f"(hi), "f"(lo));
    return r;
}

__device__ __forceinline__ uint32_t bil4(uint32_t a, uint32_t b, uint32_t c, uint32_t d,
                                         __half2 w00, __half2 w01, __half2 w10, __half2 w11) {
    __half2 r = __hmul2(*(__half2*)&a, w00);
    r = __hfma2(*(__half2*)&b, w01, r);
    r = __hfma2(*(__half2*)&c, w10, r);
    r = __hfma2(*(__half2*)&d, w11, r);
    return *(uint32_t*)&r;
}

// ---------------------------------------------------------------------------
// Kernel 0a: w_def [o][c][ki][kj] -> g_wh[k][o][c] (fp16)
// ---------------------------------------------------------------------------
__global__ void prep_wdef_kernel(const float* __restrict__ w_def) {
    int idx = blockIdx.x * 256 + threadIdx.x;
    if (idx >= 9 * OUTC * Cin) return;
    int k = idx / (OUTC * Cin);
    int rem = idx - k * (OUTC * Cin);
    int o = rem / Cin;
    int c = rem - o * Cin;
    g_wh[idx] = __float2half_rn(w_def[(o * Cin + c) * 9 + k]);
}

// ---------------------------------------------------------------------------
// Kernel 0b: w_off [j][c][ki][kj] -> g_wo_{hi,lo}[k][j][c] fp16 split
// ---------------------------------------------------------------------------
__global__ void prep_woff_kernel(const float* __restrict__ w_off) {
    int idx = blockIdx.x * 256 + threadIdx.x;      // 13824
    if (idx >= 9 * OJ * Cin) return;
    int k = idx / (OJ * Cin);
    int rem = idx - k * (OJ * Cin);
    int j = rem / Cin;
    int c = rem - j * Cin;
    float v = (j < 18) ? w_off[((size_t)j * Cin + c) * 9 + k] : 0.f;
    __half hi = __float2half_rn(v);
    float lo = v - __half2float(hi);
    g_wo_hi[idx] = hi;
    g_wo_lo[idx] = __float2half_rn(lo);
}

// ---------------------------------------------------------------------------
// Kernel 0c: transpose x NCHW -> NHWC fp16 split (g_xh + g_xl)
// ---------------------------------------------------------------------------
__global__ void __launch_bounds__(256) transpose_x_kernel(const float* __restrict__ x) {
    __shared__ float t[Cin][33];
    int tid = threadIdx.x;
    int bx = blockIdx.x;
    int wt = (bx & 7) << 5;
    int h = (bx >> 3) & (H - 1);
    int b = bx >> 11;

    const float* xb = x + (size_t)b * Cin * HW + h * W + wt;
#pragma unroll
    for (int it = 0; it < 8; it++) {
        int c = it * 8 + (tid >> 5);
        int w = tid & 31;
        t[c][w] = xb[(size_t)c * HW + w];
    }
    __syncthreads();
    size_t base = ((size_t)(b * H + h) * W + wt) * Cin;
    uint32_t* xh = (uint32_t*)(g_xh + base);
    uint32_t* xl = (uint32_t*)(g_xl + base);
#pragma unroll
    for (int it = 0; it < 4; it++) {
        int w = it * 8 + (tid >> 5);
        int c2 = tid & 31;
        float a0 = t[2 * c2][w];
        float a1 = t[2 * c2 + 1][w];
        __half h0 = __float2half_rn(a0);
        __half h1 = __float2half_rn(a1);
        __half2 hp = __halves2half2(h0, h1);
        float l0 = a0 - __half2float(h0);
        float l1 = a1 - __half2float(h1);
        xh[w * (Cin / 2) + c2] = *(uint32_t*)&hp;
        xl[w * (Cin / 2) + c2] = pack_f16x2(l0, l1);
    }
}

// ---------------------------------------------------------------------------
// Kernel 1: offsets conv, fp16 split MMA, row-reuse (R11 — protected)
// ---------------------------------------------------------------------------
#define OFF_SSM_U32 (HPX * SH32)                    // 4680 per half
#define OFF_WTAP_U32 (2 * OJ * SH32)                // 1728 per tap (hi+lo)
#define OFF_DSMEM ((2 * OFF_SSM_U32 + 2 * OFF_WTAP_U32) * 4)   // 51264 B

__global__ void __launch_bounds__(256, 4) offsets_kernel(
    const float* __restrict__ b_off)
{
    extern __shared__ uint32_t dsm[];
    uint32_t* ssm_h = dsm;                              // [130 px][c] hi
    uint32_t* ssm_l = ssm_h + OFF_SSM_U32;              // lo
    uint32_t* wbuf = ssm_l + OFF_SSM_U32;               // 2 x (hi 864 | lo 864)

    int tid = threadIdx.x;
    int bx = blockIdx.x;
    int wt = (bx & 1) << 7;
    int h = (bx >> 1) & (H - 1);
    int b = bx >> 9;

    int lane = tid & 31;
    int wid = tid >> 5;
    int r = lane & 3;
    int g = lane >> 2;
    int px0 = wid << 4;                // warp's 16-px m-tile

    float acc[3][4];
#pragma unroll
    for (int ni = 0; ni < 3; ni++)
#pragma unroll
        for (int q = 0; q < 4; q++) acc[ni][q] = 0.f;

    const uint4* xh4 = (const uint4*)(g_xh + (size_t)b * HW * Cin);
    const uint4* xl4 = (const uint4*)(g_xl + (size_t)b * HW * Cin);

    auto stageB = [&](int k, int buf) {
        uint32_t* wh = wbuf + buf * OFF_WTAP_U32;
        uint32_t* wl = wh + OJ * SH32;
        const uint4* sh = (const uint4*)(g_wo_hi + (size_t)k * OJ * Cin);
        const uint4* sl = (const uint4*)(g_wo_lo + (size_t)k * OJ * Cin);
        for (int i = tid; i < 2 * OJ * Cin / 8; i += 256) {
            int hf = (i >= OJ * Cin / 8);
            int ii = i - hf * (OJ * Cin / 8);
            int j = ii >> 3;
            int c8 = ii & 7;
            uint4 v = hf ? sl[ii] : sh[ii];
            *(uint4*)((hf ? wl : wh) + j * SH32 + c8 * 4) = v;
        }
    };

    auto mmaTap = [&](int t, int buf) {   // t = dx+1: A row = px + t
        uint32_t* wh = wbuf + buf * OFF_WTAP_U32;
        uint32_t* wl = wh + OJ * SH32;
#pragma unroll
        for (int kk = 0; kk < 4; kk++) {
            int kb = kk << 3;
            uint32_t ah[4], al[4];
            const uint32_t* arh = ssm_h + (px0 + g + t) * SH32 + kb + r;
            const uint32_t* arl = ssm_l + (px0 + g + t) * SH32 + kb + r;
            ah[0] = arh[0];
            ah[1] = arh[8 * SH32];
            ah[2] = arh[4];
            ah[3] = arh[8 * SH32 + 4];
            al[0] = arl[0];
            al[1] = arl[8 * SH32];
            al[2] = arl[4];
            al[3] = arl[8 * SH32 + 4];
#pragma unroll
            for (int ni = 0; ni < 3; ni++) {
                const uint32_t* brh = wh + (ni * 8 + g) * SH32 + kb + r;
                const uint32_t* brl = wl + (ni * 8 + g) * SH32 + kb + r;
                uint32_t bh[2] = { brh[0], brh[4] };
                uint32_t bl[2] = { brl[0], brl[4] };
                mma_f16(acc[ni], ah, bh);
                mma_f16(acc[ni], ah, bl);
                mma_f16(acc[ni], al, bh);
            }
        }
    };

    for (int rr = 0; rr < 3; rr++) {
        int y = h + rr - 1;
        bool yok = ((unsigned)y < (unsigned)H);

        __syncthreads();

        {
            uint4 z4 = make_uint4(0, 0, 0, 0);
            for (int i = tid; i < 2 * HPX * 8; i += 256) {
                int hf = (i >= HPX * 8);
                int ii = i - hf * (HPX * 8);
                int pxs = ii >> 3;
                int c8 = ii & 7;
                int xw = wt + pxs - 1;
                bool ok = yok && ((unsigned)xw < (unsigned)W);
                ptrdiff_t pix = (ptrdiff_t)y * W + xw;
                uint4 v = ok ? (hf ? xl4[pix * (Cin / 8) + c8]
                                   : xh4[pix * (Cin / 8) + c8]) : z4;
                *(uint4*)((hf ? ssm_l : ssm_h) + pxs * SH32 + c8 * 4) = v;
            }
        }
        stageB(3 * rr, 0);
        __syncthreads();

        stageB(3 * rr + 1, 1);
        mmaTap(0, 0);
        __syncthreads();

        stageB(3 * rr + 2, 0);
        mmaTap(1, 1);
        __syncthreads();

        mmaTap(2, 0);
    }

#pragma unroll
    for (int ni = 0; ni < 3; ni++) {
        int j = ni * 8 + 2 * r;
        if (j < 18) {
            float* ob = g_offs + ((size_t)b * 18 + j) * HW + h * W + wt;
            float bj = b_off[j];
            ob[px0 + g]     = acc[ni][0] + bj;
            ob[px0 + g + 8] = acc[ni][2] + bj;
        }
        if (j + 1 < 18) {
            float* ob = g_offs + ((size_t)b * 18 + j + 1) * HW + h * W + wt;
            float bj = b_off[j + 1];
            ob[px0 + g]     = acc[ni][1] + bj;
            ob[px0 + g + 8] = acc[ni][3] + bj;
        }
    }
}

// ---------------------------------------------------------------------------
// Kernel 2: deform — SOFTWARE PIPELINED: double-buffered ssm/wsm/sp,
// gather(k+1) issued before MMA(k), ONE sync per tap (was 2).
// sp packed to 8B/px: (y0,x0) s16 + (ly,lx) f16x2.
// ---------------------------------------------------------------------------
#define SSM_U32 (MTILE * SH32)            // 4608 u32 = 18432 B per buffer
#define WSM_U32 (OUTC * SH32)             // 2304 u32 =  9216 B per buffer
#define SP_U32  (MTILE * 2)               // 256 u32 = 1024 B per buffer
#define DSMEM_BYTES ((2 * SSM_U32 + 2 * WSM_U32 + 2 * SP_U32) * 4)   // 57344 B

__global__ void __launch_bounds__(256, 4) deform_kernel(
    const float* __restrict__ b_def,
    float* __restrict__ out)
{
    extern __shared__ uint32_t dsm[];
    // layout: ssm0 | ssm1 | wsm0 | wsm1 | sp0 | sp1
    uint32_t* ssmB[2] = { dsm, dsm + SSM_U32 };
    uint32_t* wsmB[2] = { dsm + 2 * SSM_U32, dsm + 2 * SSM_U32 + WSM_U32 };
    uint32_t* spB[2]  = { dsm + 2 * SSM_U32 + 2 * WSM_U32,
                          dsm + 2 * SSM_U32 + 2 * WSM_U32 + SP_U32 };

    int tid = threadIdx.x;
    int bx = blockIdx.x;
    int wt = (bx & 1) << 7;
    int h = (bx >> 1) & (H - 1);
    int b = bx >> 9;

    const float* offb = g_offs + (size_t)b * 18 * HW + h * W + wt;

    int lane = tid & 31;
    int wid = tid >> 5;
    int warp_m = (wid & 3) << 5;
    int warp_n = (wid >> 2) << 5;
    int r = lane & 3;
    int g = lane >> 2;
    int quarter = lane >> 3;           // 4 samples per warp-iter
    int cl8 = lane & 7;                // channel octet
    const uint4* xh4 = (const uint4*)(g_xh + (size_t)b * HW * Cin) + cl8;
    int px0 = wid << 4;

    float acc[2][4][4];
#pragma unroll
    for (int mi = 0; mi < 2; mi++)
#pragma unroll
        for (int ni = 0; ni < 4; ni++)
#pragma unroll
            for (int q = 0; q < 4; q++) acc[mi][ni][q] = 0.f;

    // compute packed sampling params for tap kn into spb
    auto computeSp = [&](int kn, uint32_t* spb) {
        if (tid < MTILE) {
            int px = tid;
            float offy = offb[(size_t)(2 * kn) * HW + px];
            float offx = offb[(size_t)(2 * kn + 1) * HW + px];
            float ys = (float)(h + (kn / 3) - 1) + offy;
            float xs = (float)(wt + px + (kn % 3) - 1) + offx;
            float y0f = floorf(ys);
            float x0f = floorf(xs);
            int y0 = (int)y0f;
            int x0 = (int)x0f;
            uint32_t yx = ((uint32_t)(uint16_t)(int16_t)y0)
                        | (((uint32_t)(uint16_t)(int16_t)x0) << 16);
            uint32_t ll = pack_f16x2(ys - y0f, xs - x0f);
            *(uint2*)&spb[px * 2] = make_uint2(yx, ll);
        }
    };

    auto stageW = [&](int k, uint32_t* wsm) {
        const uint4* src = (const uint4*)(g_wh + (size_t)k * OUTC * Cin);
        for (int i = tid; i < OUTC * Cin / 8; i += 256) {
            int o = i >> 3;
            int c8 = i & 7;
            *(uint4*)(wsm + o * SH32 + c8 * 4) = src[i];
        }
    };

    auto gather = [&](uint32_t* ssm, const uint32_t* spb) {
        uint4 z4 = make_uint4(0, 0, 0, 0);
#pragma unroll
        for (int s = 0; s < 4; s++) {
            int px = px0 + 4 * s + quarter;
            uint2 pp = *(const uint2*)&spb[px * 2];
            int y0 = (int)(short)(pp.x & 0xFFFF);
            int x0 = (int)(short)(pp.x >> 16);
            __half2 llh = *(__half2*)&pp.y;
            float ly = __low2float(llh);
            float lx = __high2float(llh);
            float hy = 1.f - ly, hx = 1.f - lx;
            __half2 w00h = __float2half2_rn(hy * hx);
            __half2 w01h = __float2half2_rn(hy * lx);
            __half2 w10h = __float2half2_rn(ly * hx);
            __half2 w11h = __float2half2_rn(ly * lx);
            bool y0k = ((unsigned)y0 < (unsigned)H);
            bool y1k = ((unsigned)(y0 + 1) < (unsigned)H);
            bool x0k = ((unsigned)x0 < (unsigned)W);
            bool x1k = ((unsigned)(x0 + 1) < (unsigned)W);
            const uint4* base = xh4 + ((ptrdiff_t)y0 * W + x0) * (Cin / 8);
            uint4 v00 = (y0k && x0k) ? base[0] : z4;
            uint4 v01 = (y0k && x1k) ? base[Cin / 8] : z4;
            uint4 v10 = (y1k && x0k) ? base[(ptrdiff_t)W * (Cin / 8)] : z4;
            uint4 v11 = (y1k && x1k) ? base[(ptrdiff_t)(W + 1) * (Cin / 8)] : z4;
            uint4 res;
            res.x = bil4(v00.x, v01.x, v10.x, v11.x, w00h, w01h, w10h, w11h);
            res.y = bil4(v00.y, v01.y, v10.y, v11.y, w00h, w01h, w10h, w11h);
            res.z = bil4(v00.z, v01.z, v10.z, v11.z, w00h, w01h, w10h, w11h);
            res.w = bil4(v00.w, v01.w, v10.w, v11.w, w00h, w01h, w10h, w11h);
            *(uint4*)&ssm[px * SH32 + cl8 * 4] = res;
        }
    };

    auto mmaTap = [&](const uint32_t* ssm, const uint32_t* wsm) {
#pragma unroll
        for (int kk = 0; kk < 4; kk++) {
            int kb = kk << 3;
            uint32_t a[2][4];
#pragma unroll
            for (int mi = 0; mi < 2; mi++) {
                const uint32_t* ar = ssm + (warp_m + 16 * mi + g) * SH32 + kb + r;
                a[mi][0] = ar[0];
                a[mi][1] = ar[8 * SH32];
                a[mi][2] = ar[4];
                a[mi][3] = ar[8 * SH32 + 4];
            }
            uint32_t bb[4][2];
#pragma unroll
            for (int ni = 0; ni < 4; ni++) {
                const uint32_t* br = wsm + (warp_n + ni * 8 + g) * SH32 + kb + r;
                bb[ni][0] = br[0];
                bb[ni][1] = br[4];
            }
#pragma unroll
            for (int mi = 0; mi < 2; mi++)
#pragma unroll
                for (int ni = 0; ni < 4; ni++)
                    mma_f16(acc[mi][ni], a[mi], bb[ni]);
        }
    };

    // ---- prologue ----
    computeSp(0, spB[0]);
    __syncthreads();                 // sp0 visible
    gather(ssmB[0], spB[0]);
    stageW(0, wsmB[0]);
    computeSp(1, spB[1]);
    __syncthreads();                 // ssm0/wsm0/sp1 visible

    // ---- pipelined mainloop: one sync per tap ----
#pragma unroll
    for (int k = 0; k < 9; k++) {
        if (k < 8) {
            gather(ssmB[(k + 1) & 1], spB[(k + 1) & 1]);
            stageW(k + 1, wsmB[(k + 1) & 1]);
            if (k < 7) computeSp(k + 2, spB[k & 1]);
        }
        mmaTap(ssmB[k & 1], wsmB[k & 1]);
        __syncthreads();
    }

    // ---- epilogue: bias + direct stores (NCHW out) ----
#pragma unroll
    for (int ni = 0; ni < 4; ni++) {
        int o = warp_n + ni * 8 + 2 * r;
        float bo0 = b_def[o];
        float bo1 = b_def[o + 1];
        float* ob0 = out + ((size_t)(b * OUTC + o)) * HW + h * W + wt;
        float* ob1 = ob0 + HW;
#pragma unroll
        for (int mi = 0; mi < 2; mi++) {
            int px = warp_m + mi * 16 + g;
            ob0[px]     = acc[mi][ni][0] + bo0;
            ob1[px]     = acc[mi][ni][1] + bo1;
            ob0[px + 8] = acc[mi][ni][2] + bo0;
            ob1[px + 8] = acc[mi][ni][3] + bo1;
        }
    }
}

// ---------------------------------------------------------------------------
extern "C" void kernel_launch(void* const* d_in, const int* in_sizes, int n_in,
                              void* d_out, int out_size)
{
    const float* x     = (const float*)d_in[0];
    const float* w_off = (const float*)d_in[1];
    const float* b_off = (const float*)d_in[2];
    const float* w_def = (const float*)d_in[3];
    const float* b_def = (const float*)d_in[4];
    float* out = (float*)d_out;

    cudaFuncSetAttribute(deform_kernel,
                         cudaFuncAttributeMaxDynamicSharedMemorySize, DSMEM_BYTES);
    cudaFuncSetAttribute(offsets_kernel,
                         cudaFuncAttributeMaxDynamicSharedMemorySize, OFF_DSMEM);

    prep_wdef_kernel<<<(9 * OUTC * Cin + 255) / 256, 256>>>(w_def);
    prep_woff_kernel<<<(9 * OJ * Cin + 255) / 256, 256>>>(w_off);
    transpose_x_kernel<<<Bsz * H * (W / 32), 256>>>(x);
    offsets_kernel<<<Bsz * H * (W / MTILE), 256, OFF_DSMEM>>>(b_off);
    deform_kernel<<<Bsz * H * (W / MTILE), 256, DSMEM_BYTES>>>(b_def, out);
}